// round 10
// baseline (speedup 1.0000x reference)
#include <cuda_runtime.h>
#include <cuda_fp16.h>
#include <cstdint>

#define N_NODES 100000
#define N_EDGES 1600000
#define G_GRAPHS 2048
#define NFEAT 64
#define D 32
#define SFD 512
#define BN_EPS 1e-5f
#define NBLK_SCAN 391   // ceil(100000/256)
#define NTILE 128
#define NBLK_TILE 782   // ceil(100000/128)

// ---------------- scratch (static device globals; no allocation) ----------------
__device__ __half g_ha[N_NODES * D];
__device__ __half g_hb[N_NODES * D];
__device__ __half g_hp[N_NODES * D];        // probe sink
__device__ float  g_tf[N_NODES * D];
__device__ float  g_statsf[5 * 64];
__device__ float  g_pooled[G_GRAPHS * D];
__device__ float  g_z[G_GRAPHS * 256];      // right half = solvent features
__device__ float  g_s1[G_GRAPHS * 256];
__device__ float  g_z1[G_GRAPHS * 1024];
__device__ float  g_z2[G_GRAPHS * 256];     // fc2 split-K partials
__device__ int    g_is64;
// CSR (persists across graph replays; probe reads last replay's contents)
__device__ int    g_rowptr[N_NODES + 1];
__device__ int    g_cnt[N_NODES];
__device__ int    g_col[N_EDGES];
__device__ int    g_bsum[NBLK_SCAN];

__device__ __forceinline__ int load_idx(const void* p, long i, int is64) {
    if (is64) return (int)((const long long*)p)[i];
    return ((const int*)p)[i];
}

__device__ __forceinline__ void redf(float* p, float v) {
    asm volatile("red.global.add.f32 [%0], %1;" :: "l"(p), "f"(v) : "memory");
}

// ---------------- init (zeros cnt/stats/pooled/z2/out) ----------------
__global__ void init_kernel(const void* edge, float* out) {
    int i = blockIdx.x * blockDim.x + threadIdx.x;
    if (i < N_NODES) g_cnt[i] = 0;
    if (i < G_GRAPHS * D) g_pooled[i] = 0.f;
    if (i < 5 * 64) g_statsf[i] = 0.f;
    if (i < G_GRAPHS) out[i] = 0.f;
    if (i < G_GRAPHS * 256) g_z2[i] = 0.f;
    if (i == 0) {
        const unsigned long long* p = (const unsigned long long*)edge;
        int is64 = 1;
        for (int k = 0; k < 8; k++)
            if (p[k] >= (unsigned long long)N_NODES) is64 = 0;
        g_is64 = is64;
    }
}

// ---------------- CSR build ----------------
__global__ void hist_kernel(const void* __restrict__ eidx) {
    int e = blockIdx.x * blockDim.x + threadIdx.x;
    if (e >= N_EDGES) return;
    int d = load_idx(eidx, (long)N_EDGES + e, g_is64);
    atomicAdd(&g_cnt[d], 1);
}

__global__ void scanA_kernel() {
    __shared__ int sh[256];
    int i = blockIdx.x * 256 + threadIdx.x;
    int v = (i < N_NODES) ? g_cnt[i] : 0;
    sh[threadIdx.x] = v;
    __syncthreads();
    for (int off = 128; off; off >>= 1) {
        if (threadIdx.x < off) sh[threadIdx.x] += sh[threadIdx.x + off];
        __syncthreads();
    }
    if (threadIdx.x == 0) g_bsum[blockIdx.x] = sh[0];
}

__global__ void scanC_kernel() {
    __shared__ int sbase[256];
    __shared__ int sh[256];
    int t = threadIdx.x;
    int b = blockIdx.x;
    int v = 0;
    for (int k = t; k < b; k += 256) v += g_bsum[k];
    sbase[t] = v;
    __syncthreads();
    for (int off = 128; off; off >>= 1) {
        if (t < off) sbase[t] += sbase[t + off];
        __syncthreads();
    }
    int base = sbase[0];
    int i = b * 256 + t;
    int c = (i < N_NODES) ? g_cnt[i] : 0;
    sh[t] = c;
    __syncthreads();
    for (int off = 1; off < 256; off <<= 1) {
        int a = (t >= off) ? sh[t - off] : 0;
        __syncthreads();
        sh[t] += a;
        __syncthreads();
    }
    if (i < N_NODES) {
        g_rowptr[i + 1] = base + sh[t];
        g_cnt[i] = 0;
    }
    if (i == 0) g_rowptr[0] = 0;
}

__global__ void scatter_kernel(const void* __restrict__ eidx) {
    int e = blockIdx.x * blockDim.x + threadIdx.x;
    if (e >= N_EDGES) return;
    int is64 = g_is64;
    int s = load_idx(eidx, e, is64);
    int d = load_idx(eidx, (long)N_EDGES + e, is64);
    int pos = g_rowptr[d] + atomicAdd(&g_cnt[d], 1);
    g_col[pos] = s;
}

// ---------------- PROBE: real-CSR gather mirror (clamped; dead output) ----------------
__global__ __launch_bounds__(256, 4) void probeL_kernel(const __half* __restrict__ tin,
                                                        __half* __restrict__ pout) {
    int tid = threadIdx.x;
    int lane = tid & 31, warp = tid >> 5;
    int f2 = lane & 15;
    int side = lane >> 4;
    const __half2* tin2 = (const __half2*)tin;
    int base = blockIdx.x * NTILE;
    for (int r = 0; r < 16; r++) {
        int nl = warp * 16 + r;
        int node = base + nl;
        float ax = 0.f, ay = 0.f;
        if (node < N_NODES) {
            int r0 = g_rowptr[node], r1 = g_rowptr[node + 1];
            r0 = min(max(r0, 0), N_EDGES);
            r1 = min(max(r1, r0), N_EDGES);
            if (r1 - r0 > 64) r1 = r0 + 64;      // bound vs racing CSR rebuild
            for (int i = r0; i < r1; i += 16) {
                int cc[8];
                bool vb[8];
#pragma unroll
                for (int k = 0; k < 8; k++) {
                    int idx = i + 2 * k + side;
                    vb[k] = idx < r1;
                    cc[k] = g_col[vb[k] ? idx : (r1 - 1)];
                }
                float2 vv[8];
#pragma unroll
                for (int k = 0; k < 8; k++) {
                    int c = cc[k];
                    c = (c >= 0 && c < N_NODES) ? c : 0;
                    vv[k] = __half22float2(tin2[(size_t)c * 16 + f2]);
                }
#pragma unroll
                for (int k = 0; k < 8; k++)
                    if (vb[k]) { ax += vv[k].x; ay += vv[k].y; }
            }
        }
        ax += __shfl_xor_sync(0xffffffffu, ax, 16);
        ay += __shfl_xor_sync(0xffffffffu, ay, 16);
        if (side == 0 && node < N_NODES)
            ((__half2*)pout)[(size_t)node * 16 + f2] = __floats2half2_rn(ax, ay);
    }
}

// ---------------- pre-transform as tiled GEMM: u = x @ w1a, fp16 out ----------------
__global__ __launch_bounds__(256) void pre_kernel(const float* __restrict__ x,
                                                  const float* __restrict__ w1a,
                                                  __half* __restrict__ u) {
    __shared__ float sX[NTILE * 68];
    __shared__ float sW[NFEAT * D];
    for (int i = threadIdx.x; i < NFEAT * D; i += 256) sW[i] = w1a[i];
    int base = blockIdx.x * NTILE;
    for (int i = threadIdx.x; i < NTILE * 16; i += 256) {
        int n = i >> 4, k4 = i & 15;
        int node = base + n;
        float4 v = make_float4(0.f, 0.f, 0.f, 0.f);
        if (node < N_NODES) v = ((const float4*)x)[(size_t)node * 16 + k4];
        *(float4*)&sX[n * 68 + k4 * 4] = v;
    }
    __syncthreads();
    int j0 = (threadIdx.x & 7) * 4;
    int n0 = (threadIdx.x >> 3) * 4;
    float acc[4][4];
#pragma unroll
    for (int i = 0; i < 4; i++)
#pragma unroll
        for (int j = 0; j < 4; j++) acc[i][j] = 0.f;
#pragma unroll 8
    for (int k = 0; k < NFEAT; k++) {
        float a0 = sX[(n0 + 0) * 68 + k];
        float a1 = sX[(n0 + 1) * 68 + k];
        float a2 = sX[(n0 + 2) * 68 + k];
        float a3 = sX[(n0 + 3) * 68 + k];
        float4 w = *(const float4*)&sW[k * D + j0];
        acc[0][0] = fmaf(a0, w.x, acc[0][0]); acc[0][1] = fmaf(a0, w.y, acc[0][1]);
        acc[0][2] = fmaf(a0, w.z, acc[0][2]); acc[0][3] = fmaf(a0, w.w, acc[0][3]);
        acc[1][0] = fmaf(a1, w.x, acc[1][0]); acc[1][1] = fmaf(a1, w.y, acc[1][1]);
        acc[1][2] = fmaf(a1, w.z, acc[1][2]); acc[1][3] = fmaf(a1, w.w, acc[1][3]);
        acc[2][0] = fmaf(a2, w.x, acc[2][0]); acc[2][1] = fmaf(a2, w.y, acc[2][1]);
        acc[2][2] = fmaf(a2, w.z, acc[2][2]); acc[2][3] = fmaf(a2, w.w, acc[2][3]);
        acc[3][0] = fmaf(a3, w.x, acc[3][0]); acc[3][1] = fmaf(a3, w.y, acc[3][1]);
        acc[3][2] = fmaf(a3, w.z, acc[3][2]); acc[3][3] = fmaf(a3, w.w, acc[3][3]);
    }
    __half2* u2 = (__half2*)u;
#pragma unroll
    for (int i = 0; i < 4; i++) {
        int node = base + n0 + i;
        if (node < N_NODES) {
            u2[(size_t)node * 16 + (j0 >> 1)] = __floats2half2_rn(acc[i][0], acc[i][1]);
            u2[(size_t)node * 16 + (j0 >> 1) + 1] = __floats2half2_rn(acc[i][2], acc[i][3]);
        }
    }
}

// ---------------- fused layer: predicated fp16 gather -> tile MLP -> stats ----------------
template <bool FIRST, bool OUTF32>
__global__ __launch_bounds__(256, 4) void layer_kernel(
    const __half* __restrict__ tin, const float* __restrict__ Wa,
    const float* __restrict__ ba, const float* __restrict__ Wb,
    const float* __restrict__ bb,
    const float* __restrict__ stats_in, float* __restrict__ stats_out,
    const float* __restrict__ bng, const float* __restrict__ bnb,
    __half* __restrict__ tout16, float* __restrict__ toutf) {
    __shared__ float sA[NTILE * 34];
    __shared__ float sWa[D * D];
    __shared__ float sWb[D * D];
    __shared__ float sba[D], sbb[D];
    __shared__ float sstat[64];
    int tid = threadIdx.x;
    if (!FIRST)
        for (int i = tid; i < D * D; i += 256) sWa[i] = Wa[i];
    for (int i = tid; i < D * D; i += 256) sWb[i] = Wb[i];
    if (tid < D) { sba[tid] = ba[tid]; sbb[tid] = bb[tid]; }
    if (tid < 64) sstat[tid] = 0.f;
    int lane = tid & 31, warp = tid >> 5;
    int f2 = lane & 15;
    int side = lane >> 4;
    float scx = 0.f, shx = 0.f, scy = 0.f, shy = 0.f;
    if (!FIRST) {
        int fx = 2 * f2, fy = 2 * f2 + 1;
        float Sx = stats_in[fx], Qx = stats_in[D + fx];
        float mux = Sx * (1.f / N_NODES);
        float vax = Qx * (1.f / N_NODES) - mux * mux;
        scx = rsqrtf(vax + BN_EPS) * bng[fx];
        shx = bnb[fx] - mux * scx;
        float Sy = stats_in[fy], Qy = stats_in[D + fy];
        float muy = Sy * (1.f / N_NODES);
        float vay = Qy * (1.f / N_NODES) - muy * muy;
        scy = rsqrtf(vay + BN_EPS) * bng[fy];
        shy = bnb[fy] - muy * scy;
    }
    __syncthreads();

    const __half2* tin2 = (const __half2*)tin;
    int base = blockIdx.x * NTILE;

    for (int r = 0; r < 16; r++) {
        int nl = warp * 16 + r;
        int node = base + nl;
        float ax = 0.f, ay = 0.f;
        if (node < N_NODES) {
            if (side == 0) {
                float2 v = __half22float2(tin2[(size_t)node * 16 + f2]);
                if (!FIRST) {
                    v.x = fmaxf(fmaf(v.x, scx, shx), 0.f);
                    v.y = fmaxf(fmaf(v.y, scy, shy), 0.f);
                }
                ax += v.x; ay += v.y;
            }
            int r0 = g_rowptr[node], r1 = g_rowptr[node + 1];
            for (int i = r0; i < r1; i += 16) {
                int cc[8];
                bool vb[8];
#pragma unroll
                for (int k = 0; k < 8; k++) {
                    int idx = i + 2 * k + side;
                    vb[k] = idx < r1;
                    cc[k] = g_col[vb[k] ? idx : (r1 - 1)];
                }
                float2 vv[8];
#pragma unroll
                for (int k = 0; k < 8; k++)
                    vv[k] = __half22float2(tin2[(size_t)cc[k] * 16 + f2]);
#pragma unroll
                for (int k = 0; k < 8; k++) {
                    if (vb[k]) {
                        float vx = vv[k].x, vy = vv[k].y;
                        if (!FIRST) {
                            vx = fmaxf(fmaf(vx, scx, shx), 0.f);
                            vy = fmaxf(fmaf(vy, scy, shy), 0.f);
                        }
                        ax += vx; ay += vy;
                    }
                }
            }
        }
        ax += __shfl_xor_sync(0xffffffffu, ax, 16);
        ay += __shfl_xor_sync(0xffffffffu, ay, 16);
        if (side == 0) {
            if (FIRST) {
                ax = fmaxf(ax + sba[2 * f2], 0.f);
                ay = fmaxf(ay + sba[2 * f2 + 1], 0.f);
            }
            *(float2*)&sA[nl * 34 + 2 * f2] = make_float2(ax, ay);
        }
    }
    __syncthreads();

    int j0 = (tid & 7) * 4;
    int n0 = (tid >> 3) * 4;

    if (!FIRST) {
        float acc[4][4];
#pragma unroll
        for (int i = 0; i < 4; i++)
#pragma unroll
            for (int j = 0; j < 4; j++) acc[i][j] = 0.f;
#pragma unroll
        for (int k = 0; k < D; k++) {
            float a0 = sA[(n0 + 0) * 34 + k];
            float a1 = sA[(n0 + 1) * 34 + k];
            float a2 = sA[(n0 + 2) * 34 + k];
            float a3 = sA[(n0 + 3) * 34 + k];
            float4 w = *(const float4*)&sWa[k * D + j0];
            acc[0][0] = fmaf(a0, w.x, acc[0][0]); acc[0][1] = fmaf(a0, w.y, acc[0][1]);
            acc[0][2] = fmaf(a0, w.z, acc[0][2]); acc[0][3] = fmaf(a0, w.w, acc[0][3]);
            acc[1][0] = fmaf(a1, w.x, acc[1][0]); acc[1][1] = fmaf(a1, w.y, acc[1][1]);
            acc[1][2] = fmaf(a1, w.z, acc[1][2]); acc[1][3] = fmaf(a1, w.w, acc[1][3]);
            acc[2][0] = fmaf(a2, w.x, acc[2][0]); acc[2][1] = fmaf(a2, w.y, acc[2][1]);
            acc[2][2] = fmaf(a2, w.z, acc[2][2]); acc[2][3] = fmaf(a2, w.w, acc[2][3]);
            acc[3][0] = fmaf(a3, w.x, acc[3][0]); acc[3][1] = fmaf(a3, w.y, acc[3][1]);
            acc[3][2] = fmaf(a3, w.z, acc[3][2]); acc[3][3] = fmaf(a3, w.w, acc[3][3]);
        }
        __syncthreads();
#pragma unroll
        for (int i = 0; i < 4; i++)
#pragma unroll
            for (int j = 0; j < 4; j++)
                sA[(n0 + i) * 34 + j0 + j] = fmaxf(acc[i][j] + sba[j0 + j], 0.f);
        __syncthreads();
    }

    float acc2[4][4];
#pragma unroll
    for (int i = 0; i < 4; i++)
#pragma unroll
        for (int j = 0; j < 4; j++) acc2[i][j] = 0.f;
#pragma unroll
    for (int k = 0; k < D; k++) {
        float a0 = sA[(n0 + 0) * 34 + k];
        float a1 = sA[(n0 + 1) * 34 + k];
        float a2 = sA[(n0 + 2) * 34 + k];
        float a3 = sA[(n0 + 3) * 34 + k];
        float4 w = *(const float4*)&sWb[k * D + j0];
        acc2[0][0] = fmaf(a0, w.x, acc2[0][0]); acc2[0][1] = fmaf(a0, w.y, acc2[0][1]);
        acc2[0][2] = fmaf(a0, w.z, acc2[0][2]); acc2[0][3] = fmaf(a0, w.w, acc2[0][3]);
        acc2[1][0] = fmaf(a1, w.x, acc2[1][0]); acc2[1][1] = fmaf(a1, w.y, acc2[1][1]);
        acc2[1][2] = fmaf(a1, w.z, acc2[1][2]); acc2[1][3] = fmaf(a1, w.w, acc2[1][3]);
        acc2[2][0] = fmaf(a2, w.x, acc2[2][0]); acc2[2][1] = fmaf(a2, w.y, acc2[2][1]);
        acc2[2][2] = fmaf(a2, w.z, acc2[2][2]); acc2[2][3] = fmaf(a2, w.w, acc2[2][3]);
        acc2[3][0] = fmaf(a3, w.x, acc2[3][0]); acc2[3][1] = fmaf(a3, w.y, acc2[3][1]);
        acc2[3][2] = fmaf(a3, w.z, acc2[3][2]); acc2[3][3] = fmaf(a3, w.w, acc2[3][3]);
    }
    float colS[4] = {0.f, 0.f, 0.f, 0.f};
    float colQ[4] = {0.f, 0.f, 0.f, 0.f};
    __half2* t2 = (__half2*)tout16;
#pragma unroll
    for (int i = 0; i < 4; i++) {
        int node = base + n0 + i;
        if (node < N_NODES) {
            float z0 = acc2[i][0] + sbb[j0 + 0];
            float z1 = acc2[i][1] + sbb[j0 + 1];
            float z2 = acc2[i][2] + sbb[j0 + 2];
            float z3 = acc2[i][3] + sbb[j0 + 3];
            if (OUTF32) {
                *(float4*)&toutf[(size_t)node * D + j0] = make_float4(z0, z1, z2, z3);
            } else {
                t2[(size_t)node * 16 + (j0 >> 1)] = __floats2half2_rn(z0, z1);
                t2[(size_t)node * 16 + (j0 >> 1) + 1] = __floats2half2_rn(z2, z3);
            }
            colS[0] += z0; colS[1] += z1; colS[2] += z2; colS[3] += z3;
            colQ[0] += z0 * z0; colQ[1] += z1 * z1; colQ[2] += z2 * z2; colQ[3] += z3 * z3;
        }
    }
#pragma unroll
    for (int j = 0; j < 4; j++) {
        atomicAdd(&sstat[j0 + j], colS[j]);
        atomicAdd(&sstat[32 + j0 + j], colQ[j]);
    }
    __syncthreads();
    if (tid < 64) redf(&stats_out[tid], sstat[tid]);
}

// ---------------- pooling with BN+ReLU on the fly ----------------
__global__ __launch_bounds__(256) void pool_kernel(const float* __restrict__ t,
                                                   const void* __restrict__ batch,
                                                   const float* __restrict__ stats,
                                                   const float* __restrict__ bng,
                                                   const float* __restrict__ bnb) {
    __shared__ float ssc[D], ssh[D];
    if (threadIdx.x < D) {
        int f = threadIdx.x;
        float S = stats[f], Q = stats[D + f];
        float mu = S * (1.f / N_NODES);
        float var = Q * (1.f / N_NODES) - mu * mu;
        float rs = rsqrtf(var + BN_EPS);
        float sc = rs * bng[f];
        ssc[f] = sc;
        ssh[f] = bnb[f] - mu * sc;
    }
    __syncthreads();
    int i = blockIdx.x * blockDim.x + threadIdx.x;
    if (i >= N_NODES * (D / 4)) return;
    int node = i >> 3;
    int j = i & 7;
    int b = load_idx(batch, node, g_is64);
    float4 v = ((const float4*)t)[i];
    float4 o;
    o.x = fmaxf(fmaf(v.x, ssc[j * 4 + 0], ssh[j * 4 + 0]), 0.f);
    o.y = fmaxf(fmaf(v.y, ssc[j * 4 + 1], ssh[j * 4 + 1]), 0.f);
    o.z = fmaxf(fmaf(v.z, ssc[j * 4 + 2], ssh[j * 4 + 2]), 0.f);
    o.w = fmaxf(fmaf(v.w, ssc[j * 4 + 3], ssh[j * 4 + 3]), 0.f);
    float* p = g_pooled + (size_t)b * D + j * 4;
    asm volatile("red.global.add.v4.f32 [%0], {%1,%2,%3,%4};"
                 :: "l"(p), "f"(o.x), "f"(o.y), "f"(o.z), "f"(o.w) : "memory");
}

// ---------------- big tiled fp32 GEMM: 128x128 tile, 8x8/thread, double-buffered ----------------
template <bool ACC, bool RELU>
__global__ __launch_bounds__(256) void gemmT_kernel(
    const float* __restrict__ A, int lda,
    const float* __restrict__ B,
    const float* __restrict__ bias,
    const float* __restrict__ Cin,
    float* __restrict__ C,
    int N, int K, int ldc) {
    __shared__ float As[2][8][128];
    __shared__ float Bs[2][8][128];
    int tid = threadIdx.x;
    int tx = tid & 15;
    int ty = tid >> 4;
    int row0 = blockIdx.y * 128;
    int col0 = blockIdx.x * 128;
    int arow = tid >> 1, ak = (tid & 1) * 4;
    int brow = tid >> 5, bcol = (tid & 31) * 4;

    float acc[8][8];
#pragma unroll
    for (int i = 0; i < 8; i++)
#pragma unroll
        for (int j = 0; j < 8; j++) acc[i][j] = 0.f;

    const float* Ap = A + (size_t)(row0 + arow) * lda + ak;
    {
        float4 av = *(const float4*)Ap;
        As[0][ak + 0][arow] = av.x; As[0][ak + 1][arow] = av.y;
        As[0][ak + 2][arow] = av.z; As[0][ak + 3][arow] = av.w;
        float4 bv = *(const float4*)&B[(size_t)brow * N + col0 + bcol];
        *(float4*)&Bs[0][brow][bcol] = bv;
    }
    __syncthreads();
    int nk = K / 8;
    for (int t = 0; t < nk; t++) {
        int cur = t & 1, nxt = cur ^ 1;
        if (t + 1 < nk) {
            float4 av = *(const float4*)(Ap + (t + 1) * 8);
            As[nxt][ak + 0][arow] = av.x; As[nxt][ak + 1][arow] = av.y;
            As[nxt][ak + 2][arow] = av.z; As[nxt][ak + 3][arow] = av.w;
            float4 bv = *(const float4*)&B[(size_t)((t + 1) * 8 + brow) * N + col0 + bcol];
            *(float4*)&Bs[nxt][brow][bcol] = bv;
        }
#pragma unroll
        for (int k = 0; k < 8; k++) {
            float4 a0 = *(const float4*)&As[cur][k][ty * 8];
            float4 a1 = *(const float4*)&As[cur][k][ty * 8 + 4];
            float4 b0 = *(const float4*)&Bs[cur][k][tx * 8];
            float4 b1 = *(const float4*)&Bs[cur][k][tx * 8 + 4];
            float a_[8] = {a0.x, a0.y, a0.z, a0.w, a1.x, a1.y, a1.z, a1.w};
            float b_[8] = {b0.x, b0.y, b0.z, b0.w, b1.x, b1.y, b1.z, b1.w};
#pragma unroll
            for (int i = 0; i < 8; i++)
#pragma unroll
                for (int j = 0; j < 8; j++) acc[i][j] = fmaf(a_[i], b_[j], acc[i][j]);
        }
        __syncthreads();
    }
#pragma unroll
    for (int i = 0; i < 8; i++) {
        int rr = row0 + ty * 8 + i;
#pragma unroll
        for (int j = 0; j < 8; j++) {
            int cc = col0 + tx * 8 + j;
            float v = acc[i][j];
            if (ACC) v += Cin[(size_t)rr * ldc + cc];
            else v += bias[cc];
            if (RELU) v = fmaxf(v, 0.f);
            C[(size_t)rr * ldc + cc] = v;
        }
    }
}

// ---------------- fused fcg + fc1_top ----------------
#define GTOP_SMEM ((128 * 128 + 128 * 33 + 32 * 128 + 2 * 8 * 128 + 128) * 4)
__global__ __launch_bounds__(256) void gemmTop_kernel(
    const float* __restrict__ pooled,
    const float* __restrict__ fcgw, const float* __restrict__ fcgb,
    const float* __restrict__ Btop,
    float* __restrict__ z1) {
    extern __shared__ float dsm[];
    float* sGt = dsm;
    float* sP  = sGt + 128 * 128;
    float* sW  = sP + 128 * 33;
    float* BsP = sW + 32 * 128;
    float* sbf = BsP + 2 * 8 * 128;
    int tid = threadIdx.x;
    int row0 = blockIdx.y * 128;
    int col0 = blockIdx.x * 128;

    for (int r = 0; r < 16; r++) {
        int lin = tid + 256 * r;
        int m = lin >> 5, j = lin & 31;
        sP[m * 33 + j] = pooled[(size_t)(row0 + m) * D + j];
    }
    for (int i = tid; i < 32 * 128; i += 256) sW[i] = fcgw[i];
    if (tid < 128) sbf[tid] = fcgb[tid];
    __syncthreads();

    {
        int tyc = tid >> 4, txc = tid & 15;
        int m0 = tyc * 8, k0c = txc * 8;
        float acc[8][8];
#pragma unroll
        for (int i = 0; i < 8; i++)
#pragma unroll
            for (int t = 0; t < 8; t++) acc[i][t] = 0.f;
        for (int j = 0; j < 32; j++) {
            float a_[8], w_[8];
#pragma unroll
            for (int i = 0; i < 8; i++) a_[i] = sP[(m0 + i) * 33 + j];
#pragma unroll
            for (int t = 0; t < 8; t++) w_[t] = sW[j * 128 + k0c + t];
#pragma unroll
            for (int i = 0; i < 8; i++)
#pragma unroll
                for (int t = 0; t < 8; t++) acc[i][t] = fmaf(a_[i], w_[t], acc[i][t]);
        }
#pragma unroll
        for (int t = 0; t < 8; t++)
#pragma unroll
            for (int i = 0; i < 8; i++)
                sGt[(k0c + t) * 128 + m0 + i] = fmaxf(acc[i][t] + sbf[k0c + t], 0.f);
    }
    __syncthreads();

    int tx = tid & 15;
    int ty = tid >> 4;
    int brow = tid >> 5, bcol = (tid & 31) * 4;
    float acc[8][8];
#pragma unroll
    for (int i = 0; i < 8; i++)
#pragma unroll
        for (int j = 0; j < 8; j++) acc[i][j] = 0.f;
    {
        float4 bv = *(const float4*)&Btop[(size_t)brow * 1024 + col0 + bcol];
        *(float4*)&BsP[(0 * 8 + brow) * 128 + bcol] = bv;
    }
    __syncthreads();
    for (int t = 0; t < 16; t++) {
        int cur = t & 1, nxt = cur ^ 1;
        if (t + 1 < 16) {
            float4 bv = *(const float4*)&Btop[(size_t)((t + 1) * 8 + brow) * 1024 + col0 + bcol];
            *(float4*)&BsP[(nxt * 8 + brow) * 128 + bcol] = bv;
        }
#pragma unroll
        for (int k = 0; k < 8; k++) {
            int ka = t * 8 + k;
            float4 a0 = *(const float4*)&sGt[ka * 128 + ty * 8];
            float4 a1 = *(const float4*)&sGt[ka * 128 + ty * 8 + 4];
            float4 b0 = *(const float4*)&BsP[(cur * 8 + k) * 128 + tx * 8];
            float4 b1 = *(const float4*)&BsP[(cur * 8 + k) * 128 + tx * 8 + 4];
            float a_[8] = {a0.x, a0.y, a0.z, a0.w, a1.x, a1.y, a1.z, a1.w};
            float b_[8] = {b0.x, b0.y, b0.z, b0.w, b1.x, b1.y, b1.z, b1.w};
#pragma unroll
            for (int i = 0; i < 8; i++)
#pragma unroll
                for (int j = 0; j < 8; j++) acc[i][j] = fmaf(a_[i], b_[j], acc[i][j]);
        }
        __syncthreads();
    }
#pragma unroll
    for (int i = 0; i < 8; i++) {
        int rr = row0 + ty * 8 + i;
#pragma unroll
        for (int j = 0; j < 8; j++) {
            int cc = col0 + tx * 8 + j;
            float v = acc[i][j] + z1[(size_t)rr * 1024 + cc];
            z1[(size_t)rr * 1024 + cc] = fmaxf(v, 0.f);
        }
    }
}

// ---------------- fc2 split-K: z2 += z1[:, kslice] @ fc2_w[kslice, :] ----------------
__global__ __launch_bounds__(256) void fc2sk_kernel(
    const float* __restrict__ A,       // z1 [2048,1024]
    const float* __restrict__ B) {     // fc2_w [1024,256]
    __shared__ float As[16][64];
    __shared__ float Bs[16][64];
    int tid = threadIdx.x;
    int tx = tid & 15;
    int ty = tid >> 4;
    int row0 = blockIdx.y * 64;
    int col0 = blockIdx.x * 64;
    int kbase = blockIdx.z * 256;
    const int K = 1024, Np = 256;
    float acc[4][4];
#pragma unroll
    for (int i = 0; i < 4; i++)
#pragma unroll
        for (int j = 0; j < 4; j++) acc[i][j] = 0.f;

    for (int kt = kbase; kt < kbase + 256; kt += 16) {
#pragma unroll
        for (int r = 0; r < 4; r++) {
            int idx = tid + r * 256;
            int m = idx >> 4, k = idx & 15;
            As[k][m] = A[(size_t)(row0 + m) * K + kt + k];
            int bk = idx >> 6, c = idx & 63;
            Bs[bk][c] = B[(size_t)(kt + bk) * Np + col0 + c];
        }
        __syncthreads();
#pragma unroll
        for (int k = 0; k < 16; k++) {
            float4 av = *(const float4*)&As[k][ty * 4];
            float4 bv = *(const float4*)&Bs[k][tx * 4];
            float a_[4] = {av.x, av.y, av.z, av.w};
            float b_[4] = {bv.x, bv.y, bv.z, bv.w};
#pragma unroll
            for (int i = 0; i < 4; i++)
#pragma unroll
                for (int j = 0; j < 4; j++) acc[i][j] = fmaf(a_[i], b_[j], acc[i][j]);
        }
        __syncthreads();
    }
#pragma unroll
    for (int i = 0; i < 4; i++) {
        int rr = row0 + ty * 4 + i;
#pragma unroll
        for (int j = 0; j < 4; j++) {
            int cc = col0 + tx * 4 + j;
            atomicAdd(&g_z2[(size_t)rr * 256 + cc], acc[i][j]);
        }
    }
}

// ---------------- relu(z2 + fc2_b) dot out_w + out_b ----------------
__global__ void out2_kernel(const float* __restrict__ fc2b, const float* __restrict__ ow,
                            const float* __restrict__ ob, float* __restrict__ out) {
    int warp = threadIdx.x >> 5;
    int lane = threadIdx.x & 31;
    int row = blockIdx.x * (blockDim.x >> 5) + warp;
    if (row >= G_GRAPHS) return;
    const float* z = g_z2 + (size_t)row * 256;
    float s = 0.f;
#pragma unroll
    for (int k = 0; k < 8; k++) {
        int c = lane + k * 32;
        float v = fmaxf(z[c] + fc2b[c], 0.f);
        s = fmaf(v, ow[c], s);
    }
#pragma unroll
    for (int o = 16; o; o >>= 1) s += __shfl_down_sync(0xffffffffu, s, o);
    if (lane == 0) out[row] = s + ob[0];
}

// ---------------- launch ----------------
extern "C" void kernel_launch(void* const* d_in, const int* in_sizes, int n_in,
                              void* d_out, int out_size) {
    const float* x     = (const float*)d_in[0];
    const void*  eidx  = d_in[1];
    const void*  batch = d_in[2];
    const float* sfp   = (const float*)d_in[3];
    const float* w1a   = (const float*)d_in[4];
    const float* b1a   = (const float*)d_in[5];
    const float* ws_a  = (const float*)d_in[6];
    const float* bs_a  = (const float*)d_in[7];
    const float* ws_b  = (const float*)d_in[8];
    const float* bs_b  = (const float*)d_in[9];
    const float* bn_g  = (const float*)d_in[10];
    const float* bn_b  = (const float*)d_in[11];
    const float* fcg_w = (const float*)d_in[12];
    const float* fcg_b = (const float*)d_in[13];
    const float* fs1_w = (const float*)d_in[14];
    const float* fs1_b = (const float*)d_in[15];
    const float* fs2_w = (const float*)d_in[16];
    const float* fs2_b = (const float*)d_in[17];
    const float* fc1_w = (const float*)d_in[18];
    const float* fc1_b = (const float*)d_in[19];
    const float* fc2_w = (const float*)d_in[20];
    const float* fc2_b = (const float*)d_in[21];
    const float* out_w = (const float*)d_in[22];
    const float* out_b = (const float*)d_in[23];
    float* out = (float*)d_out;

    __half *ha, *hb, *hp;
    float *tf, *pooled, *z, *s1, *z1, *statsf;
    cudaGetSymbolAddress((void**)&ha, g_ha);
    cudaGetSymbolAddress((void**)&hb, g_hb);
    cudaGetSymbolAddress((void**)&hp, g_hp);
    cudaGetSymbolAddress((void**)&tf, g_tf);
    cudaGetSymbolAddress((void**)&pooled, g_pooled);
    cudaGetSymbolAddress((void**)&z, g_z);
    cudaGetSymbolAddress((void**)&s1, g_s1);
    cudaGetSymbolAddress((void**)&z1, g_z1);
    cudaGetSymbolAddress((void**)&statsf, g_statsf);

    static cudaStream_t sA = nullptr, sB = nullptr, sP = nullptr;
    static cudaEvent_t evRoot = nullptr, evA = nullptr, evB = nullptr, evP = nullptr;
    if (!sA) {
        cudaStreamCreateWithFlags(&sA, cudaStreamNonBlocking);
        cudaStreamCreateWithFlags(&sB, cudaStreamNonBlocking);
        cudaStreamCreateWithFlags(&sP, cudaStreamNonBlocking);
        cudaEventCreateWithFlags(&evRoot, cudaEventDisableTiming);
        cudaEventCreateWithFlags(&evA, cudaEventDisableTiming);
        cudaEventCreateWithFlags(&evB, cudaEventDisableTiming);
        cudaEventCreateWithFlags(&evP, cudaEventDisableTiming);
        cudaFuncSetAttribute(gemmTop_kernel,
                             cudaFuncAttributeMaxDynamicSharedMemorySize, GTOP_SMEM);
    }

    const int TB = 256;

    // ---- fork ----
    cudaEventRecord(evRoot, 0);
    cudaStreamWaitEvent(sA, evRoot, 0);
    cudaStreamWaitEvent(sB, evRoot, 0);
    cudaStreamWaitEvent(sP, evRoot, 0);

    // 0: init (main) — covers z2 (524288 elems)
    init_kernel<<<(G_GRAPHS * 256 + TB - 1) / TB, TB>>>(eidx, out);

    // Branch B: fs1(1) -> fs2(2)
    gemmT_kernel<false, true><<<dim3(2, 16), 256, 0, sB>>>(
        sfp, SFD, fs1_w, fs1_b, nullptr, s1, 256, 512, 256);
    gemmT_kernel<false, true><<<dim3(1, 16), 256, 0, sB>>>(
        s1, 256, fs2_w, fs2_b, nullptr, z + 128, 128, 256, 256);

    // 3: PROBE — real-CSR gather mirror (captured by ncu)
    probeL_kernel<<<NBLK_TILE, 256, 0, sP>>>(ha, hp);
    cudaEventRecord(evP, sP);

    // 4: fc1_bottom (sB)
    gemmT_kernel<false, false><<<dim3(8, 16), 256, 0, sB>>>(
        z + 128, 256, fc1_w + 128 * 1024, fc1_b, nullptr, z1, 1024, 128, 1024);
    cudaEventRecord(evB, sB);

    // 5: pre-transform (sA)
    pre_kernel<<<NBLK_TILE, 256, 0, sA>>>(x, w1a, ha);
    cudaEventRecord(evA, sA);

    // Main: CSR build
    hist_kernel<<<(N_EDGES + TB - 1) / TB, TB>>>(eidx);
    scanA_kernel<<<NBLK_SCAN, 256>>>();
    scanC_kernel<<<NBLK_SCAN, 256>>>();
    scatter_kernel<<<(N_EDGES + TB - 1) / TB, TB>>>(eidx);

    // layers
    cudaStreamWaitEvent(0, evA, 0);
    cudaStreamWaitEvent(0, evP, 0);      // probe reads ha; layer1 writes hb, next overwrites ha
    layer_kernel<true, false><<<NBLK_TILE, 256>>>(ha, nullptr, b1a, ws_b, bs_b,
                                                  nullptr, statsf, nullptr, nullptr,
                                                  hb, nullptr);
    __half* tin = hb;
    __half* tout = ha;
    for (int l = 1; l < 4; l++) {
        layer_kernel<false, false><<<NBLK_TILE, 256>>>(
            tin, ws_a + (l - 1) * D * D, bs_a + (l - 1) * D,
            ws_b + l * D * D, bs_b + l * D,
            statsf + (l - 1) * 64, statsf + l * 64,
            bn_g + (l - 1) * D, bn_b + (l - 1) * D, tout, nullptr);
        __half* tmp = tin; tin = tout; tout = tmp;
    }
    layer_kernel<false, true><<<NBLK_TILE, 256>>>(
        tin, ws_a + 3 * D * D, bs_a + 3 * D,
        ws_b + 4 * D * D, bs_b + 4 * D,
        statsf + 3 * 64, statsf + 4 * 64,
        bn_g + 3 * D, bn_b + 3 * D, nullptr, tf);

    // pooling
    pool_kernel<<<(N_NODES * 8 + TB - 1) / TB, TB>>>(tf, batch, statsf + 4 * 64,
                                                     bn_g + 4 * D, bn_b + 4 * D);

    // head tail
    cudaStreamWaitEvent(0, evB, 0);
    gemmTop_kernel<<<dim3(8, 16), 256, GTOP_SMEM>>>(pooled, fcg_w, fcg_b, fc1_w, z1);
    fc2sk_kernel<<<dim3(4, 32, 4), 256>>>(z1, fc2_w);
    out2_kernel<<<G_GRAPHS / 8, 256>>>(fc2_b, out_w, out_b, out);
}

// round 11
// speedup vs baseline: 1.0881x; 1.0881x over previous
#include <cuda_runtime.h>
#include <cuda_fp16.h>
#include <cstdint>

#define N_NODES 100000
#define N_EDGES 1600000
#define G_GRAPHS 2048
#define NFEAT 64
#define D 32
#define SFD 512
#define BN_EPS 1e-5f
#define NBLK_SCAN 391   // ceil(100000/256)
#define NTILE 128
#define NBLK_TILE 782   // ceil(100000/128)

// ---------------- scratch (static device globals; no allocation) ----------------
__device__ __half g_ha[N_NODES * D];
__device__ __half g_hb[N_NODES * D];
__device__ float  g_tf[N_NODES * D];
__device__ float  g_statsf[5 * 64];
__device__ float  g_pooled[G_GRAPHS * D];
__device__ float  g_z[G_GRAPHS * 256];      // [gfeat | solvent]
__device__ float  g_s1[G_GRAPHS * 256];
__device__ float  g_z1[G_GRAPHS * 1024];
__device__ float  g_z2[G_GRAPHS * 256];     // fc2 split-K partials
__device__ int    g_is64;
// CSR
__device__ int    g_rowptr[N_NODES + 1];
__device__ int    g_cnt[N_NODES];
__device__ int    g_col[N_EDGES];
__device__ int    g_bsum[NBLK_SCAN];

__device__ __forceinline__ int load_idx(const void* p, long i, int is64) {
    if (is64) return (int)((const long long*)p)[i];
    return ((const int*)p)[i];
}

__device__ __forceinline__ void redf(float* p, float v) {
    asm volatile("red.global.add.f32 [%0], %1;" :: "l"(p), "f"(v) : "memory");
}

// ---------------- init ----------------
__global__ void init_kernel(const void* edge, float* out) {
    int i = blockIdx.x * blockDim.x + threadIdx.x;
    if (i < N_NODES) g_cnt[i] = 0;
    if (i < G_GRAPHS * D) g_pooled[i] = 0.f;
    if (i < 5 * 64) g_statsf[i] = 0.f;
    if (i < G_GRAPHS) out[i] = 0.f;
    if (i < G_GRAPHS * 256) g_z2[i] = 0.f;
    if (i == 0) {
        const unsigned long long* p = (const unsigned long long*)edge;
        int is64 = 1;
        for (int k = 0; k < 8; k++)
            if (p[k] >= (unsigned long long)N_NODES) is64 = 0;
        g_is64 = is64;
    }
}

// ---------------- CSR build ----------------
__global__ void hist_kernel(const void* __restrict__ eidx) {
    int e = blockIdx.x * blockDim.x + threadIdx.x;
    if (e >= N_EDGES) return;
    int d = load_idx(eidx, (long)N_EDGES + e, g_is64);
    atomicAdd(&g_cnt[d], 1);
}

__global__ void scanA_kernel() {
    __shared__ int sh[256];
    int i = blockIdx.x * 256 + threadIdx.x;
    int v = (i < N_NODES) ? g_cnt[i] : 0;
    sh[threadIdx.x] = v;
    __syncthreads();
    for (int off = 128; off; off >>= 1) {
        if (threadIdx.x < off) sh[threadIdx.x] += sh[threadIdx.x + off];
        __syncthreads();
    }
    if (threadIdx.x == 0) g_bsum[blockIdx.x] = sh[0];
}

__global__ void scanC_kernel() {
    __shared__ int sbase[256];
    __shared__ int sh[256];
    int t = threadIdx.x;
    int b = blockIdx.x;
    int v = 0;
    for (int k = t; k < b; k += 256) v += g_bsum[k];
    sbase[t] = v;
    __syncthreads();
    for (int off = 128; off; off >>= 1) {
        if (t < off) sbase[t] += sbase[t + off];
        __syncthreads();
    }
    int base = sbase[0];
    int i = b * 256 + t;
    int c = (i < N_NODES) ? g_cnt[i] : 0;
    sh[t] = c;
    __syncthreads();
    for (int off = 1; off < 256; off <<= 1) {
        int a = (t >= off) ? sh[t - off] : 0;
        __syncthreads();
        sh[t] += a;
        __syncthreads();
    }
    if (i < N_NODES) {
        g_rowptr[i + 1] = base + sh[t];
        g_cnt[i] = 0;
    }
    if (i == 0) g_rowptr[0] = 0;
}

__global__ void scatter_kernel(const void* __restrict__ eidx) {
    int e = blockIdx.x * blockDim.x + threadIdx.x;
    if (e >= N_EDGES) return;
    int is64 = g_is64;
    int s = load_idx(eidx, e, is64);
    int d = load_idx(eidx, (long)N_EDGES + e, is64);
    int pos = g_rowptr[d] + atomicAdd(&g_cnt[d], 1);
    g_col[pos] = s;
}

// ---------------- pre-transform as tiled GEMM: u = x @ w1a, fp16 out ----------------
__global__ __launch_bounds__(256) void pre_kernel(const float* __restrict__ x,
                                                  const float* __restrict__ w1a,
                                                  __half* __restrict__ u) {
    __shared__ float sX[NTILE * 68];
    __shared__ float sW[NFEAT * D];
    for (int i = threadIdx.x; i < NFEAT * D; i += 256) sW[i] = w1a[i];
    int base = blockIdx.x * NTILE;
    for (int i = threadIdx.x; i < NTILE * 16; i += 256) {
        int n = i >> 4, k4 = i & 15;
        int node = base + n;
        float4 v = make_float4(0.f, 0.f, 0.f, 0.f);
        if (node < N_NODES) v = ((const float4*)x)[(size_t)node * 16 + k4];
        *(float4*)&sX[n * 68 + k4 * 4] = v;
    }
    __syncthreads();
    int j0 = (threadIdx.x & 7) * 4;
    int n0 = (threadIdx.x >> 3) * 4;
    float acc[4][4];
#pragma unroll
    for (int i = 0; i < 4; i++)
#pragma unroll
        for (int j = 0; j < 4; j++) acc[i][j] = 0.f;
#pragma unroll 8
    for (int k = 0; k < NFEAT; k++) {
        float a0 = sX[(n0 + 0) * 68 + k];
        float a1 = sX[(n0 + 1) * 68 + k];
        float a2 = sX[(n0 + 2) * 68 + k];
        float a3 = sX[(n0 + 3) * 68 + k];
        float4 w = *(const float4*)&sW[k * D + j0];
        acc[0][0] = fmaf(a0, w.x, acc[0][0]); acc[0][1] = fmaf(a0, w.y, acc[0][1]);
        acc[0][2] = fmaf(a0, w.z, acc[0][2]); acc[0][3] = fmaf(a0, w.w, acc[0][3]);
        acc[1][0] = fmaf(a1, w.x, acc[1][0]); acc[1][1] = fmaf(a1, w.y, acc[1][1]);
        acc[1][2] = fmaf(a1, w.z, acc[1][2]); acc[1][3] = fmaf(a1, w.w, acc[1][3]);
        acc[2][0] = fmaf(a2, w.x, acc[2][0]); acc[2][1] = fmaf(a2, w.y, acc[2][1]);
        acc[2][2] = fmaf(a2, w.z, acc[2][2]); acc[2][3] = fmaf(a2, w.w, acc[2][3]);
        acc[3][0] = fmaf(a3, w.x, acc[3][0]); acc[3][1] = fmaf(a3, w.y, acc[3][1]);
        acc[3][2] = fmaf(a3, w.z, acc[3][2]); acc[3][3] = fmaf(a3, w.w, acc[3][3]);
    }
    __half2* u2 = (__half2*)u;
#pragma unroll
    for (int i = 0; i < 4; i++) {
        int node = base + n0 + i;
        if (node < N_NODES) {
            u2[(size_t)node * 16 + (j0 >> 1)] = __floats2half2_rn(acc[i][0], acc[i][1]);
            u2[(size_t)node * 16 + (j0 >> 1) + 1] = __floats2half2_rn(acc[i][2], acc[i][3]);
        }
    }
}

// ---------------- fused layer: predicated fp16 gather -> tile MLP -> stats ----------------
template <bool FIRST, bool OUTF32>
__global__ __launch_bounds__(256, 4) void layer_kernel(
    const __half* __restrict__ tin, const float* __restrict__ Wa,
    const float* __restrict__ ba, const float* __restrict__ Wb,
    const float* __restrict__ bb,
    const float* __restrict__ stats_in, float* __restrict__ stats_out,
    const float* __restrict__ bng, const float* __restrict__ bnb,
    __half* __restrict__ tout16, float* __restrict__ toutf) {
    __shared__ float sA[NTILE * 34];
    __shared__ float sWa[D * D];
    __shared__ float sWb[D * D];
    __shared__ float sba[D], sbb[D];
    __shared__ float sstat[64];
    int tid = threadIdx.x;
    if (!FIRST)
        for (int i = tid; i < D * D; i += 256) sWa[i] = Wa[i];
    for (int i = tid; i < D * D; i += 256) sWb[i] = Wb[i];
    if (tid < D) { sba[tid] = ba[tid]; sbb[tid] = bb[tid]; }
    if (tid < 64) sstat[tid] = 0.f;
    int lane = tid & 31, warp = tid >> 5;
    int f2 = lane & 15;
    int side = lane >> 4;
    float scx = 0.f, shx = 0.f, scy = 0.f, shy = 0.f;
    if (!FIRST) {
        int fx = 2 * f2, fy = 2 * f2 + 1;
        float Sx = stats_in[fx], Qx = stats_in[D + fx];
        float mux = Sx * (1.f / N_NODES);
        float vax = Qx * (1.f / N_NODES) - mux * mux;
        scx = rsqrtf(vax + BN_EPS) * bng[fx];
        shx = bnb[fx] - mux * scx;
        float Sy = stats_in[fy], Qy = stats_in[D + fy];
        float muy = Sy * (1.f / N_NODES);
        float vay = Qy * (1.f / N_NODES) - muy * muy;
        scy = rsqrtf(vay + BN_EPS) * bng[fy];
        shy = bnb[fy] - muy * scy;
    }
    __syncthreads();

    const __half2* tin2 = (const __half2*)tin;
    int base = blockIdx.x * NTILE;

    for (int r = 0; r < 16; r++) {
        int nl = warp * 16 + r;
        int node = base + nl;
        float ax = 0.f, ay = 0.f;
        if (node < N_NODES) {
            if (side == 0) {
                float2 v = __half22float2(tin2[(size_t)node * 16 + f2]);
                if (!FIRST) {
                    v.x = fmaxf(fmaf(v.x, scx, shx), 0.f);
                    v.y = fmaxf(fmaf(v.y, scy, shy), 0.f);
                }
                ax += v.x; ay += v.y;
            }
            int r0 = g_rowptr[node], r1 = g_rowptr[node + 1];
            for (int i = r0; i < r1; i += 16) {
                int cc[8];
                bool vb[8];
#pragma unroll
                for (int k = 0; k < 8; k++) {
                    int idx = i + 2 * k + side;
                    vb[k] = idx < r1;
                    cc[k] = g_col[vb[k] ? idx : (r1 - 1)];
                }
                float2 vv[8];
#pragma unroll
                for (int k = 0; k < 8; k++)
                    vv[k] = __half22float2(tin2[(size_t)cc[k] * 16 + f2]);
#pragma unroll
                for (int k = 0; k < 8; k++) {
                    if (vb[k]) {
                        float vx = vv[k].x, vy = vv[k].y;
                        if (!FIRST) {
                            vx = fmaxf(fmaf(vx, scx, shx), 0.f);
                            vy = fmaxf(fmaf(vy, scy, shy), 0.f);
                        }
                        ax += vx; ay += vy;
                    }
                }
            }
        }
        ax += __shfl_xor_sync(0xffffffffu, ax, 16);
        ay += __shfl_xor_sync(0xffffffffu, ay, 16);
        if (side == 0) {
            if (FIRST) {
                ax = fmaxf(ax + sba[2 * f2], 0.f);
                ay = fmaxf(ay + sba[2 * f2 + 1], 0.f);
            }
            *(float2*)&sA[nl * 34 + 2 * f2] = make_float2(ax, ay);
        }
    }
    __syncthreads();

    int j0 = (tid & 7) * 4;
    int n0 = (tid >> 3) * 4;

    if (!FIRST) {
        float acc[4][4];
#pragma unroll
        for (int i = 0; i < 4; i++)
#pragma unroll
            for (int j = 0; j < 4; j++) acc[i][j] = 0.f;
#pragma unroll
        for (int k = 0; k < D; k++) {
            float a0 = sA[(n0 + 0) * 34 + k];
            float a1 = sA[(n0 + 1) * 34 + k];
            float a2 = sA[(n0 + 2) * 34 + k];
            float a3 = sA[(n0 + 3) * 34 + k];
            float4 w = *(const float4*)&sWa[k * D + j0];
            acc[0][0] = fmaf(a0, w.x, acc[0][0]); acc[0][1] = fmaf(a0, w.y, acc[0][1]);
            acc[0][2] = fmaf(a0, w.z, acc[0][2]); acc[0][3] = fmaf(a0, w.w, acc[0][3]);
            acc[1][0] = fmaf(a1, w.x, acc[1][0]); acc[1][1] = fmaf(a1, w.y, acc[1][1]);
            acc[1][2] = fmaf(a1, w.z, acc[1][2]); acc[1][3] = fmaf(a1, w.w, acc[1][3]);
            acc[2][0] = fmaf(a2, w.x, acc[2][0]); acc[2][1] = fmaf(a2, w.y, acc[2][1]);
            acc[2][2] = fmaf(a2, w.z, acc[2][2]); acc[2][3] = fmaf(a2, w.w, acc[2][3]);
            acc[3][0] = fmaf(a3, w.x, acc[3][0]); acc[3][1] = fmaf(a3, w.y, acc[3][1]);
            acc[3][2] = fmaf(a3, w.z, acc[3][2]); acc[3][3] = fmaf(a3, w.w, acc[3][3]);
        }
        __syncthreads();
#pragma unroll
        for (int i = 0; i < 4; i++)
#pragma unroll
            for (int j = 0; j < 4; j++)
                sA[(n0 + i) * 34 + j0 + j] = fmaxf(acc[i][j] + sba[j0 + j], 0.f);
        __syncthreads();
    }

    float acc2[4][4];
#pragma unroll
    for (int i = 0; i < 4; i++)
#pragma unroll
        for (int j = 0; j < 4; j++) acc2[i][j] = 0.f;
#pragma unroll
    for (int k = 0; k < D; k++) {
        float a0 = sA[(n0 + 0) * 34 + k];
        float a1 = sA[(n0 + 1) * 34 + k];
        float a2 = sA[(n0 + 2) * 34 + k];
        float a3 = sA[(n0 + 3) * 34 + k];
        float4 w = *(const float4*)&sWb[k * D + j0];
        acc2[0][0] = fmaf(a0, w.x, acc2[0][0]); acc2[0][1] = fmaf(a0, w.y, acc2[0][1]);
        acc2[0][2] = fmaf(a0, w.z, acc2[0][2]); acc2[0][3] = fmaf(a0, w.w, acc2[0][3]);
        acc2[1][0] = fmaf(a1, w.x, acc2[1][0]); acc2[1][1] = fmaf(a1, w.y, acc2[1][1]);
        acc2[1][2] = fmaf(a1, w.z, acc2[1][2]); acc2[1][3] = fmaf(a1, w.w, acc2[1][3]);
        acc2[2][0] = fmaf(a2, w.x, acc2[2][0]); acc2[2][1] = fmaf(a2, w.y, acc2[2][1]);
        acc2[2][2] = fmaf(a2, w.z, acc2[2][2]); acc2[2][3] = fmaf(a2, w.w, acc2[2][3]);
        acc2[3][0] = fmaf(a3, w.x, acc2[3][0]); acc2[3][1] = fmaf(a3, w.y, acc2[3][1]);
        acc2[3][2] = fmaf(a3, w.z, acc2[3][2]); acc2[3][3] = fmaf(a3, w.w, acc2[3][3]);
    }
    float colS[4] = {0.f, 0.f, 0.f, 0.f};
    float colQ[4] = {0.f, 0.f, 0.f, 0.f};
    __half2* t2 = (__half2*)tout16;
#pragma unroll
    for (int i = 0; i < 4; i++) {
        int node = base + n0 + i;
        if (node < N_NODES) {
            float z0 = acc2[i][0] + sbb[j0 + 0];
            float z1 = acc2[i][1] + sbb[j0 + 1];
            float z2 = acc2[i][2] + sbb[j0 + 2];
            float z3 = acc2[i][3] + sbb[j0 + 3];
            if (OUTF32) {
                *(float4*)&toutf[(size_t)node * D + j0] = make_float4(z0, z1, z2, z3);
            } else {
                t2[(size_t)node * 16 + (j0 >> 1)] = __floats2half2_rn(z0, z1);
                t2[(size_t)node * 16 + (j0 >> 1) + 1] = __floats2half2_rn(z2, z3);
            }
            colS[0] += z0; colS[1] += z1; colS[2] += z2; colS[3] += z3;
            colQ[0] += z0 * z0; colQ[1] += z1 * z1; colQ[2] += z2 * z2; colQ[3] += z3 * z3;
        }
    }
#pragma unroll
    for (int j = 0; j < 4; j++) {
        atomicAdd(&sstat[j0 + j], colS[j]);
        atomicAdd(&sstat[32 + j0 + j], colQ[j]);
    }
    __syncthreads();
    if (tid < 64) redf(&stats_out[tid], sstat[tid]);
}

// ---------------- pooling with BN+ReLU on the fly ----------------
__global__ __launch_bounds__(256) void pool_kernel(const float* __restrict__ t,
                                                   const void* __restrict__ batch,
                                                   const float* __restrict__ stats,
                                                   const float* __restrict__ bng,
                                                   const float* __restrict__ bnb) {
    __shared__ float ssc[D], ssh[D];
    if (threadIdx.x < D) {
        int f = threadIdx.x;
        float S = stats[f], Q = stats[D + f];
        float mu = S * (1.f / N_NODES);
        float var = Q * (1.f / N_NODES) - mu * mu;
        float rs = rsqrtf(var + BN_EPS);
        float sc = rs * bng[f];
        ssc[f] = sc;
        ssh[f] = bnb[f] - mu * sc;
    }
    __syncthreads();
    int i = blockIdx.x * blockDim.x + threadIdx.x;
    if (i >= N_NODES * (D / 4)) return;
    int node = i >> 3;
    int j = i & 7;
    int b = load_idx(batch, node, g_is64);
    float4 v = ((const float4*)t)[i];
    float4 o;
    o.x = fmaxf(fmaf(v.x, ssc[j * 4 + 0], ssh[j * 4 + 0]), 0.f);
    o.y = fmaxf(fmaf(v.y, ssc[j * 4 + 1], ssh[j * 4 + 1]), 0.f);
    o.z = fmaxf(fmaf(v.z, ssc[j * 4 + 2], ssh[j * 4 + 2]), 0.f);
    o.w = fmaxf(fmaf(v.w, ssc[j * 4 + 3], ssh[j * 4 + 3]), 0.f);
    float* p = g_pooled + (size_t)b * D + j * 4;
    asm volatile("red.global.add.v4.f32 [%0], {%1,%2,%3,%4};"
                 :: "l"(p), "f"(o.x), "f"(o.y), "f"(o.z), "f"(o.w) : "memory");
}

// ---------------- tiled fp32 GEMM 64x64, 4x4 per thread, lda parameterized ----------------
// ACC: C = relu?(C + A@B) ; !ACC: C = relu?(A@B + bias)
template <bool ACC, bool RELU>
__global__ __launch_bounds__(256) void gemm64_kernel(
    const float* __restrict__ A, int lda,
    const float* __restrict__ B,
    const float* __restrict__ bias,
    float* __restrict__ C,
    int Np, int K, int ldc) {
    __shared__ float As[16][64];
    __shared__ float Bs[16][64];
    int tid = threadIdx.x;
    int tx = tid & 15;
    int ty = tid >> 4;
    int row0 = blockIdx.y * 64;
    int col0 = blockIdx.x * 64;
    float acc[4][4];
#pragma unroll
    for (int i = 0; i < 4; i++)
#pragma unroll
        for (int j = 0; j < 4; j++) acc[i][j] = 0.f;

    for (int kt = 0; kt < K; kt += 16) {
#pragma unroll
        for (int r = 0; r < 4; r++) {
            int idx = tid + r * 256;
            int m = idx >> 4, k = idx & 15;
            As[k][m] = A[(size_t)(row0 + m) * lda + kt + k];
            int bk = idx >> 6, c = idx & 63;
            Bs[bk][c] = B[(size_t)(kt + bk) * Np + col0 + c];
        }
        __syncthreads();
#pragma unroll
        for (int k = 0; k < 16; k++) {
            float4 av = *(const float4*)&As[k][ty * 4];
            float4 bv = *(const float4*)&Bs[k][tx * 4];
            float a_[4] = {av.x, av.y, av.z, av.w};
            float b_[4] = {bv.x, bv.y, bv.z, bv.w};
#pragma unroll
            for (int i = 0; i < 4; i++)
#pragma unroll
                for (int j = 0; j < 4; j++) acc[i][j] = fmaf(a_[i], b_[j], acc[i][j]);
        }
        __syncthreads();
    }
#pragma unroll
    for (int i = 0; i < 4; i++) {
        int rr = row0 + ty * 4 + i;
#pragma unroll
        for (int j = 0; j < 4; j++) {
            int cc = col0 + tx * 4 + j;
            float v = acc[i][j];
            if (ACC) v += C[(size_t)rr * ldc + cc];
            else v += bias[cc];
            if (RELU) v = fmaxf(v, 0.f);
            C[(size_t)rr * ldc + cc] = v;
        }
    }
}

// ---------------- fc2 split-K: g_z2 += z1[:, kslice] @ fc2_w[kslice, :] ----------------
__global__ __launch_bounds__(256) void fc2sk_kernel(
    const float* __restrict__ A, const float* __restrict__ B) {
    __shared__ float As[16][64];
    __shared__ float Bs[16][64];
    int tid = threadIdx.x;
    int tx = tid & 15;
    int ty = tid >> 4;
    int row0 = blockIdx.y * 64;
    int col0 = blockIdx.x * 64;
    int kbase = blockIdx.z * 256;
    const int K = 1024, Np = 256;
    float acc[4][4];
#pragma unroll
    for (int i = 0; i < 4; i++)
#pragma unroll
        for (int j = 0; j < 4; j++) acc[i][j] = 0.f;

    for (int kt = kbase; kt < kbase + 256; kt += 16) {
#pragma unroll
        for (int r = 0; r < 4; r++) {
            int idx = tid + r * 256;
            int m = idx >> 4, k = idx & 15;
            As[k][m] = A[(size_t)(row0 + m) * K + kt + k];
            int bk = idx >> 6, c = idx & 63;
            Bs[bk][c] = B[(size_t)(kt + bk) * Np + col0 + c];
        }
        __syncthreads();
#pragma unroll
        for (int k = 0; k < 16; k++) {
            float4 av = *(const float4*)&As[k][ty * 4];
            float4 bv = *(const float4*)&Bs[k][tx * 4];
            float a_[4] = {av.x, av.y, av.z, av.w};
            float b_[4] = {bv.x, bv.y, bv.z, bv.w};
#pragma unroll
            for (int i = 0; i < 4; i++)
#pragma unroll
                for (int j = 0; j < 4; j++) acc[i][j] = fmaf(a_[i], b_[j], acc[i][j]);
        }
        __syncthreads();
    }
#pragma unroll
    for (int i = 0; i < 4; i++) {
        int rr = row0 + ty * 4 + i;
#pragma unroll
        for (int j = 0; j < 4; j++) {
            int cc = col0 + tx * 4 + j;
            atomicAdd(&g_z2[(size_t)rr * 256 + cc], acc[i][j]);
        }
    }
}

// ---------------- relu(z2 + fc2_b) dot out_w + out_b ----------------
__global__ void out2_kernel(const float* __restrict__ fc2b, const float* __restrict__ ow,
                            const float* __restrict__ ob, float* __restrict__ out) {
    int warp = threadIdx.x >> 5;
    int lane = threadIdx.x & 31;
    int row = blockIdx.x * (blockDim.x >> 5) + warp;
    if (row >= G_GRAPHS) return;
    const float* z = g_z2 + (size_t)row * 256;
    float s = 0.f;
#pragma unroll
    for (int k = 0; k < 8; k++) {
        int c = lane + k * 32;
        float v = fmaxf(z[c] + fc2b[c], 0.f);
        s = fmaf(v, ow[c], s);
    }
#pragma unroll
    for (int o = 16; o; o >>= 1) s += __shfl_down_sync(0xffffffffu, s, o);
    if (lane == 0) out[row] = s + ob[0];
}

// ---------------- launch ----------------
extern "C" void kernel_launch(void* const* d_in, const int* in_sizes, int n_in,
                              void* d_out, int out_size) {
    const float* x     = (const float*)d_in[0];
    const void*  eidx  = d_in[1];
    const void*  batch = d_in[2];
    const float* sfp   = (const float*)d_in[3];
    const float* w1a   = (const float*)d_in[4];
    const float* b1a   = (const float*)d_in[5];
    const float* ws_a  = (const float*)d_in[6];
    const float* bs_a  = (const float*)d_in[7];
    const float* ws_b  = (const float*)d_in[8];
    const float* bs_b  = (const float*)d_in[9];
    const float* bn_g  = (const float*)d_in[10];
    const float* bn_b  = (const float*)d_in[11];
    const float* fcg_w = (const float*)d_in[12];
    const float* fcg_b = (const float*)d_in[13];
    const float* fs1_w = (const float*)d_in[14];
    const float* fs1_b = (const float*)d_in[15];
    const float* fs2_w = (const float*)d_in[16];
    const float* fs2_b = (const float*)d_in[17];
    const float* fc1_w = (const float*)d_in[18];
    const float* fc1_b = (const float*)d_in[19];
    const float* fc2_w = (const float*)d_in[20];
    const float* fc2_b = (const float*)d_in[21];
    const float* out_w = (const float*)d_in[22];
    const float* out_b = (const float*)d_in[23];
    float* out = (float*)d_out;

    __half *ha, *hb;
    float *tf, *pooled, *z, *s1, *z1, *statsf;
    cudaGetSymbolAddress((void**)&ha, g_ha);
    cudaGetSymbolAddress((void**)&hb, g_hb);
    cudaGetSymbolAddress((void**)&tf, g_tf);
    cudaGetSymbolAddress((void**)&pooled, g_pooled);
    cudaGetSymbolAddress((void**)&z, g_z);
    cudaGetSymbolAddress((void**)&s1, g_s1);
    cudaGetSymbolAddress((void**)&z1, g_z1);
    cudaGetSymbolAddress((void**)&statsf, g_statsf);

    static cudaStream_t sA = nullptr, sB = nullptr;
    static cudaEvent_t evRoot = nullptr, evA = nullptr, evB = nullptr;
    if (!sA) {
        cudaStreamCreateWithFlags(&sA, cudaStreamNonBlocking);
        cudaStreamCreateWithFlags(&sB, cudaStreamNonBlocking);
        cudaEventCreateWithFlags(&evRoot, cudaEventDisableTiming);
        cudaEventCreateWithFlags(&evA, cudaEventDisableTiming);
        cudaEventCreateWithFlags(&evB, cudaEventDisableTiming);
    }

    const int TB = 256;

    // ---- fork ----
    cudaEventRecord(evRoot, 0);
    cudaStreamWaitEvent(sA, evRoot, 0);
    cudaStreamWaitEvent(sB, evRoot, 0);

    // 0: init
    init_kernel<<<(G_GRAPHS * 256 + TB - 1) / TB, TB>>>(eidx, out);

    // Branch B: fs1(1) -> fs2(2) -> fc1_bottom(3, captured by ncu)
    gemm64_kernel<false, true><<<dim3(4, 32), 256, 0, sB>>>(
        sfp, SFD, fs1_w, fs1_b, s1, 256, 512, 256);
    gemm64_kernel<false, true><<<dim3(2, 32), 256, 0, sB>>>(
        s1, 256, fs2_w, fs2_b, z + 128, 128, 256, 256);
    gemm64_kernel<false, false><<<dim3(16, 32), 256, 0, sB>>>(
        z + 128, 256, fc1_w + 128 * 1024, fc1_b, z1, 1024, 128, 1024);
    cudaEventRecord(evB, sB);

    // Branch A: pre-transform (4)
    pre_kernel<<<NBLK_TILE, 256, 0, sA>>>(x, w1a, ha);
    cudaEventRecord(evA, sA);

    // Main: CSR build
    hist_kernel<<<(N_EDGES + TB - 1) / TB, TB>>>(eidx);
    scanA_kernel<<<NBLK_SCAN, 256>>>();
    scanC_kernel<<<NBLK_SCAN, 256>>>();
    scatter_kernel<<<(N_EDGES + TB - 1) / TB, TB>>>(eidx);

    // layers
    cudaStreamWaitEvent(0, evA, 0);
    layer_kernel<true, false><<<NBLK_TILE, 256>>>(ha, nullptr, b1a, ws_b, bs_b,
                                                  nullptr, statsf, nullptr, nullptr,
                                                  hb, nullptr);
    __half* tin = hb;
    __half* tout = ha;
    for (int l = 1; l < 4; l++) {
        layer_kernel<false, false><<<NBLK_TILE, 256>>>(
            tin, ws_a + (l - 1) * D * D, bs_a + (l - 1) * D,
            ws_b + l * D * D, bs_b + l * D,
            statsf + (l - 1) * 64, statsf + l * 64,
            bn_g + (l - 1) * D, bn_b + (l - 1) * D, tout, nullptr);
        __half* tmp = tin; tin = tout; tout = tmp;
    }
    layer_kernel<false, true><<<NBLK_TILE, 256>>>(
        tin, ws_a + 3 * D * D, bs_a + 3 * D,
        ws_b + 4 * D * D, bs_b + 4 * D,
        statsf + 3 * 64, statsf + 4 * 64,
        bn_g + 3 * D, bn_b + 3 * D, nullptr, tf);

    // pooling -> gfeat
    pool_kernel<<<(N_NODES * 8 + TB - 1) / TB, TB>>>(tf, batch, statsf + 4 * 64,
                                                     bn_g + 4 * D, bn_b + 4 * D);
    gemm64_kernel<false, true><<<dim3(2, 32), 256>>>(
        pooled, D, fcg_w, fcg_b, z, 128, 32, 256);

    // join solvent branch; fc1_top (accumulate into z1) ; fc2 split-K ; out
    cudaStreamWaitEvent(0, evB, 0);
    gemm64_kernel<true, true><<<dim3(16, 32), 256>>>(
        z, 256, fc1_w, nullptr, z1, 1024, 128, 1024);
    fc2sk_kernel<<<dim3(4, 32, 4), 256>>>(z1, fc2_w);
    out2_kernel<<<G_GRAPHS / 8, 256>>>(fc2_b, out_w, out_b, out);
}

// round 12
// speedup vs baseline: 1.1356x; 1.0437x over previous
#include <cuda_runtime.h>
#include <cuda_fp16.h>
#include <cstdint>

#define N_NODES 100000
#define N_EDGES 1600000
#define G_GRAPHS 2048
#define NFEAT 64
#define D 32
#define SFD 512
#define BN_EPS 1e-5f
#define NBLK_SCAN 391
#define NTILE 128
#define NBLK_TILE 782

__device__ __half g_ha[N_NODES * D];
__device__ __half g_hb[N_NODES * D];
__device__ float  g_tf[N_NODES * D];
__device__ float  g_statsf[5 * 64];
__device__ float  g_pooled[G_GRAPHS * D];
__device__ float  g_z[G_GRAPHS * 256];
__device__ float  g_s1[G_GRAPHS * 256];
__device__ float  g_z1[G_GRAPHS * 1024];
__device__ float  g_z2[G_GRAPHS * 256];
__device__ int    g_is64;
__device__ int    g_rowptr[N_NODES + 1];
__device__ int    g_cnt[N_NODES];
__device__ int    g_col[N_EDGES];
__device__ int    g_bsum[NBLK_SCAN];

__device__ __forceinline__ int load_idx(const void* p, long i, int is64) {
    if (is64) return (int)((const long long*)p)[i];
    return ((const int*)p)[i];
}

__device__ __forceinline__ void redf(float* p, float v) {
    asm volatile("red.global.add.f32 [%0], %1;" :: "l"(p), "f"(v) : "memory");
}

__global__ void init_kernel(const void* edge, float* out) {
    int i = blockIdx.x * blockDim.x + threadIdx.x;
    if (i < N_NODES) g_cnt[i] = 0;
    if (i < G_GRAPHS * D) g_pooled[i] = 0.f;
    if (i < 5 * 64) g_statsf[i] = 0.f;
    if (i < G_GRAPHS) out[i] = 0.f;
    if (i < G_GRAPHS * 256) g_z2[i] = 0.f;
    if (i == 0) {
        const unsigned long long* p = (const unsigned long long*)edge;
        int is64 = 1;
        for (int k = 0; k < 8; k++)
            if (p[k] >= (unsigned long long)N_NODES) is64 = 0;
        g_is64 = is64;
    }
}

__global__ void hist_kernel(const void* __restrict__ eidx) {
    int e = blockIdx.x * blockDim.x + threadIdx.x;
    if (e >= N_EDGES) return;
    int d = load_idx(eidx, (long)N_EDGES + e, g_is64);
    atomicAdd(&g_cnt[d], 1);
}

__global__ void scanA_kernel() {
    __shared__ int sh[256];
    int i = blockIdx.x * 256 + threadIdx.x;
    int v = (i < N_NODES) ? g_cnt[i] : 0;
    sh[threadIdx.x] = v;
    __syncthreads();
    for (int off = 128; off; off >>= 1) {
        if (threadIdx.x < off) sh[threadIdx.x] += sh[threadIdx.x + off];
        __syncthreads();
    }
    if (threadIdx.x == 0) g_bsum[blockIdx.x] = sh[0];
}

__global__ void scanC_kernel() {
    __shared__ int sbase[256];
    __shared__ int sh[256];
    int t = threadIdx.x;
    int b = blockIdx.x;
    int v = 0;
    for (int k = t; k < b; k += 256) v += g_bsum[k];
    sbase[t] = v;
    __syncthreads();
    for (int off = 128; off; off >>= 1) {
        if (t < off) sbase[t] += sbase[t + off];
        __syncthreads();
    }
    int base = sbase[0];
    int i = b * 256 + t;
    int c = (i < N_NODES) ? g_cnt[i] : 0;
    sh[t] = c;
    __syncthreads();
    for (int off = 1; off < 256; off <<= 1) {
        int a = (t >= off) ? sh[t - off] : 0;
        __syncthreads();
        sh[t] += a;
        __syncthreads();
    }
    if (i < N_NODES) {
        g_rowptr[i + 1] = base + sh[t];
        g_cnt[i] = 0;
    }
    if (i == 0) g_rowptr[0] = 0;
}

__global__ void scatter_kernel(const void* __restrict__ eidx) {
    int e = blockIdx.x * blockDim.x + threadIdx.x;
    if (e >= N_EDGES) return;
    int is64 = g_is64;
    int s = load_idx(eidx, e, is64);
    int d = load_idx(eidx, (long)N_EDGES + e, is64);
    int pos = g_rowptr[d] + atomicAdd(&g_cnt[d], 1);
    g_col[pos] = s;
}

__global__ __launch_bounds__(256) void pre_kernel(const float* __restrict__ x,
                                                  const float* __restrict__ w1a,
                                                  __half* __restrict__ u) {
    __shared__ float sX[NTILE * 68];
    __shared__ float sW[NFEAT * D];
    for (int i = threadIdx.x; i < NFEAT * D; i += 256) sW[i] = w1a[i];
    int base = blockIdx.x * NTILE;
    for (int i = threadIdx.x; i < NTILE * 16; i += 256) {
        int n = i >> 4, k4 = i & 15;
        int node = base + n;
        float4 v = make_float4(0.f, 0.f, 0.f, 0.f);
        if (node < N_NODES) v = ((const float4*)x)[(size_t)node * 16 + k4];
        *(float4*)&sX[n * 68 + k4 * 4] = v;
    }
    __syncthreads();
    int j0 = (threadIdx.x & 7) * 4;
    int n0 = (threadIdx.x >> 3) * 4;
    float acc[4][4];
#pragma unroll
    for (int i = 0; i < 4; i++)
#pragma unroll
        for (int j = 0; j < 4; j++) acc[i][j] = 0.f;
#pragma unroll 8
    for (int k = 0; k < NFEAT; k++) {
        float a0 = sX[(n0 + 0) * 68 + k];
        float a1 = sX[(n0 + 1) * 68 + k];
        float a2 = sX[(n0 + 2) * 68 + k];
        float a3 = sX[(n0 + 3) * 68 + k];
        float4 w = *(const float4*)&sW[k * D + j0];
        acc[0][0] = fmaf(a0, w.x, acc[0][0]); acc[0][1] = fmaf(a0, w.y, acc[0][1]);
        acc[0][2] = fmaf(a0, w.z, acc[0][2]); acc[0][3] = fmaf(a0, w.w, acc[0][3]);
        acc[1][0] = fmaf(a1, w.x, acc[1][0]); acc[1][1] = fmaf(a1, w.y, acc[1][1]);
        acc[1][2] = fmaf(a1, w.z, acc[1][2]); acc[1][3] = fmaf(a1, w.w, acc[1][3]);
        acc[2][0] = fmaf(a2, w.x, acc[2][0]); acc[2][1] = fmaf(a2, w.y, acc[2][1]);
        acc[2][2] = fmaf(a2, w.z, acc[2][2]); acc[2][3] = fmaf(a2, w.w, acc[2][3]);
        acc[3][0] = fmaf(a3, w.x, acc[3][0]); acc[3][1] = fmaf(a3, w.y, acc[3][1]);
        acc[3][2] = fmaf(a3, w.z, acc[3][2]); acc[3][3] = fmaf(a3, w.w, acc[3][3]);
    }
    __half2* u2 = (__half2*)u;
#pragma unroll
    for (int i = 0; i < 4; i++) {
        int node = base + n0 + i;
        if (node < N_NODES) {
            u2[(size_t)node * 16 + (j0 >> 1)] = __floats2half2_rn(acc[i][0], acc[i][1]);
            u2[(size_t)node * 16 + (j0 >> 1) + 1] = __floats2half2_rn(acc[i][2], acc[i][3]);
        }
    }
}

template <bool FIRST, bool OUTF32>
__global__ __launch_bounds__(256, 4) void layer_kernel(
    const __half* __restrict__ tin, const float* __restrict__ Wa,
    const float* __restrict__ ba, const float* __restrict__ Wb,
    const float* __restrict__ bb,
    const float* __restrict__ stats_in, float* __restrict__ stats_out,
    const float* __restrict__ bng, const float* __restrict__ bnb,
    __half* __restrict__ tout16, float* __restrict__ toutf) {
    __shared__ float sA[NTILE * 34];
    __shared__ float sWa[D * D];
    __shared__ float sWb[D * D];
    __shared__ float sba[D], sbb[D];
    __shared__ float sstat[64];
    int tid = threadIdx.x;
    if (!FIRST)
        for (int i = tid; i < D * D; i += 256) sWa[i] = Wa[i];
    for (int i = tid; i < D * D; i += 256) sWb[i] = Wb[i];
    if (tid < D) { sba[tid] = ba[tid]; sbb[tid] = bb[tid]; }
    if (tid < 64) sstat[tid] = 0.f;
    int lane = tid & 31, warp = tid >> 5;
    int f2 = lane & 15;
    int side = lane >> 4;
    float scx = 0.f, shx = 0.f, scy = 0.f, shy = 0.f;
    if (!FIRST) {
        int fx = 2 * f2, fy = 2 * f2 + 1;
        float Sx = stats_in[fx], Qx = stats_in[D + fx];
        float mux = Sx * (1.f / N_NODES);
        float vax = Qx * (1.f / N_NODES) - mux * mux;
        scx = rsqrtf(vax + BN_EPS) * bng[fx];
        shx = bnb[fx] - mux * scx;
        float Sy = stats_in[fy], Qy = stats_in[D + fy];
        float muy = Sy * (1.f / N_NODES);
        float vay = Qy * (1.f / N_NODES) - muy * muy;
        scy = rsqrtf(vay + BN_EPS) * bng[fy];
        shy = bnb[fy] - muy * scy;
    }
    __syncthreads();

    const __half2* tin2 = (const __half2*)tin;
    int base = blockIdx.x * NTILE;

    for (int r = 0; r < 16; r++) {
        int nl = warp * 16 + r;
        int node = base + nl;
        float ax = 0.f, ay = 0.f;
        if (node < N_NODES) {
            if (side == 0) {
                float2 v = __half22float2(tin2[(size_t)node * 16 + f2]);
                if (!FIRST) {
                    v.x = fmaxf(fmaf(v.x, scx, shx), 0.f);
                    v.y = fmaxf(fmaf(v.y, scy, shy), 0.f);
                }
                ax += v.x; ay += v.y;
            }
            int r0 = g_rowptr[node], r1 = g_rowptr[node + 1];
            for (int i = r0; i < r1; i += 16) {
                int cc[8];
                bool vb[8];
#pragma unroll
                for (int k = 0; k < 8; k++) {
                    int idx = i + 2 * k + side;
                    vb[k] = idx < r1;
                    cc[k] = g_col[vb[k] ? idx : (r1 - 1)];
                }
                float2 vv[8];
#pragma unroll
                for (int k = 0; k < 8; k++)
                    vv[k] = __half22float2(tin2[(size_t)cc[k] * 16 + f2]);
#pragma unroll
                for (int k = 0; k < 8; k++) {
                    if (vb[k]) {
                        float vx = vv[k].x, vy = vv[k].y;
                        if (!FIRST) {
                            vx = fmaxf(fmaf(vx, scx, shx), 0.f);
                            vy = fmaxf(fmaf(vy, scy, shy), 0.f);
                        }
                        ax += vx; ay += vy;
                    }
                }
            }
        }
        ax += __shfl_xor_sync(0xffffffffu, ax, 16);
        ay += __shfl_xor_sync(0xffffffffu, ay, 16);
        if (side == 0) {
            if (FIRST) {
                ax = fmaxf(ax + sba[2 * f2], 0.f);
                ay = fmaxf(ay + sba[2 * f2 + 1], 0.f);
            }
            *(float2*)&sA[nl * 34 + 2 * f2] = make_float2(ax, ay);
        }
    }
    __syncthreads();

    int j0 = (tid & 7) * 4;
    int n0 = (tid >> 3) * 4;

    if (!FIRST) {
        float acc[4][4];
#pragma unroll
        for (int i = 0; i < 4; i++)
#pragma unroll
            for (int j = 0; j < 4; j++) acc[i][j] = 0.f;
#pragma unroll
        for (int k = 0; k < D; k++) {
            float a0 = sA[(n0 + 0) * 34 + k];
            float a1 = sA[(n0 + 1) * 34 + k];
            float a2 = sA[(n0 + 2) * 34 + k];
            float a3 = sA[(n0 + 3) * 34 + k];
            float4 w = *(const float4*)&sWa[k * D + j0];
            acc[0][0] = fmaf(a0, w.x, acc[0][0]); acc[0][1] = fmaf(a0, w.y, acc[0][1]);
            acc[0][2] = fmaf(a0, w.z, acc[0][2]); acc[0][3] = fmaf(a0, w.w, acc[0][3]);
            acc[1][0] = fmaf(a1, w.x, acc[1][0]); acc[1][1] = fmaf(a1, w.y, acc[1][1]);
            acc[1][2] = fmaf(a1, w.z, acc[1][2]); acc[1][3] = fmaf(a1, w.w, acc[1][3]);
            acc[2][0] = fmaf(a2, w.x, acc[2][0]); acc[2][1] = fmaf(a2, w.y, acc[2][1]);
            acc[2][2] = fmaf(a2, w.z, acc[2][2]); acc[2][3] = fmaf(a2, w.w, acc[2][3]);
            acc[3][0] = fmaf(a3, w.x, acc[3][0]); acc[3][1] = fmaf(a3, w.y, acc[3][1]);
            acc[3][2] = fmaf(a3, w.z, acc[3][2]); acc[3][3] = fmaf(a3, w.w, acc[3][3]);
        }
        __syncthreads();
#pragma unroll
        for (int i = 0; i < 4; i++)
#pragma unroll
            for (int j = 0; j < 4; j++)
                sA[(n0 + i) * 34 + j0 + j] = fmaxf(acc[i][j] + sba[j0 + j], 0.f);
        __syncthreads();
    }

    float acc2[4][4];
#pragma unroll
    for (int i = 0; i < 4; i++)
#pragma unroll
        for (int j = 0; j < 4; j++) acc2[i][j] = 0.f;
#pragma unroll
    for (int k = 0; k < D; k++) {
        float a0 = sA[(n0 + 0) * 34 + k];
        float a1 = sA[(n0 + 1) * 34 + k];
        float a2 = sA[(n0 + 2) * 34 + k];
        float a3 = sA[(n0 + 3) * 34 + k];
        float4 w = *(const float4*)&sWb[k * D + j0];
        acc2[0][0] = fmaf(a0, w.x, acc2[0][0]); acc2[0][1] = fmaf(a0, w.y, acc2[0][1]);
        acc2[0][2] = fmaf(a0, w.z, acc2[0][2]); acc2[0][3] = fmaf(a0, w.w, acc2[0][3]);
        acc2[1][0] = fmaf(a1, w.x, acc2[1][0]); acc2[1][1] = fmaf(a1, w.y, acc2[1][1]);
        acc2[1][2] = fmaf(a1, w.z, acc2[1][2]); acc2[1][3] = fmaf(a1, w.w, acc2[1][3]);
        acc2[2][0] = fmaf(a2, w.x, acc2[2][0]); acc2[2][1] = fmaf(a2, w.y, acc2[2][1]);
        acc2[2][2] = fmaf(a2, w.z, acc2[2][2]); acc2[2][3] = fmaf(a2, w.w, acc2[2][3]);
        acc2[3][0] = fmaf(a3, w.x, acc2[3][0]); acc2[3][1] = fmaf(a3, w.y, acc2[3][1]);
        acc2[3][2] = fmaf(a3, w.z, acc2[3][2]); acc2[3][3] = fmaf(a3, w.w, acc2[3][3]);
    }
    float colS[4] = {0.f, 0.f, 0.f, 0.f};
    float colQ[4] = {0.f, 0.f, 0.f, 0.f};
    __half2* t2 = (__half2*)tout16;
#pragma unroll
    for (int i = 0; i < 4; i++) {
        int node = base + n0 + i;
        if (node < N_NODES) {
            float z0 = acc2[i][0] + sbb[j0 + 0];
            float z1 = acc2[i][1] + sbb[j0 + 1];
            float z2 = acc2[i][2] + sbb[j0 + 2];
            float z3 = acc2[i][3] + sbb[j0 + 3];
            if (OUTF32) {
                *(float4*)&toutf[(size_t)node * D + j0] = make_float4(z0, z1, z2, z3);
            } else {
                t2[(size_t)node * 16 + (j0 >> 1)] = __floats2half2_rn(z0, z1);
                t2[(size_t)node * 16 + (j0 >> 1) + 1] = __floats2half2_rn(z2, z3);
            }
            colS[0] += z0; colS[1] += z1; colS[2] += z2; colS[3] += z3;
            colQ[0] += z0 * z0; colQ[1] += z1 * z1; colQ[2] += z2 * z2; colQ[3] += z3 * z3;
        }
    }
#pragma unroll
    for (int j = 0; j < 4; j++) {
        atomicAdd(&sstat[j0 + j], colS[j]);
        atomicAdd(&sstat[32 + j0 + j], colQ[j]);
    }
    __syncthreads();
    if (tid < 64) redf(&stats_out[tid], sstat[tid]);
}

__global__ __launch_bounds__(256) void pool_kernel(const float* __restrict__ t,
                                                   const void* __restrict__ batch,
                                                   const float* __restrict__ stats,
                                                   const float* __restrict__ bng,
                                                   const float* __restrict__ bnb) {
    __shared__ float ssc[D], ssh[D];
    if (threadIdx.x < D) {
        int f = threadIdx.x;
        float S = stats[f], Q = stats[D + f];
        float mu = S * (1.f / N_NODES);
        float var = Q * (1.f / N_NODES) - mu * mu;
        float rs = rsqrtf(var + BN_EPS);
        float sc = rs * bng[f];
        ssc[f] = sc;
        ssh[f] = bnb[f] - mu * sc;
    }
    __syncthreads();
    int i = blockIdx.x * blockDim.x + threadIdx.x;
    if (i >= N_NODES * (D / 4)) return;
    int node = i >> 3;
    int j = i & 7;
    int b = load_idx(batch, node, g_is64);
    float4 v = ((const float4*)t)[i];
    float4 o;
    o.x = fmaxf(fmaf(v.x, ssc[j * 4 + 0], ssh[j * 4 + 0]), 0.f);
    o.y = fmaxf(fmaf(v.y, ssc[j * 4 + 1], ssh[j * 4 + 1]), 0.f);
    o.z = fmaxf(fmaf(v.z, ssc[j * 4 + 2], ssh[j * 4 + 2]), 0.f);
    o.w = fmaxf(fmaf(v.w, ssc[j * 4 + 3], ssh[j * 4 + 3]), 0.f);
    float* p = g_pooled + (size_t)b * D + j * 4;
    asm volatile("red.global.add.v4.f32 [%0], {%1,%2,%3,%4};"
                 :: "l"(p), "f"(o.x), "f"(o.y), "f"(o.z), "f"(o.w) : "memory");
}

template <bool ACC, bool RELU>
__global__ __launch_bounds__(256) void gemm64_kernel(
    const float* __restrict__ A, int lda,
    const float* __restrict__ B,
    const float* __restrict__ bias,
    float* __restrict__ C,
    int Np, int K, int ldc) {
    __shared__ float As[16][64];
    __shared__ float Bs[16][64];
    int tid = threadIdx.x;
    int tx = tid & 15;
    int ty = tid >> 4;
    int row0 = blockIdx.y * 64;
    int col0 = blockIdx.x * 64;
    float acc[4][4];
#pragma unroll
    for (int i = 0; i < 4; i++)
#pragma unroll
        for (int j = 0; j < 4; j++) acc[i][j] = 0.f;

    for (int kt = 0; kt < K; kt += 16) {
#pragma unroll
        for (int r = 0; r < 4; r++) {
            int idx = tid + r * 256;
            int m = idx >> 4, k = idx & 15;
            As[k][m] = A[(size_t)(row0 + m) * lda + kt + k];
            int bk = idx >> 6, c = idx & 63;
            Bs[bk][c] = B[(size_t)(kt + bk) * Np + col0 + c];
        }
        __syncthreads();
#pragma unroll
        for (int k = 0; k < 16; k++) {
            float4 av = *(const float4*)&As[k][ty * 4];
            float4 bv = *(const float4*)&Bs[k][tx * 4];
            float a_[4] = {av.x, av.y, av.z, av.w};
            float b_[4] = {bv.x, bv.y, bv.z, bv.w};
#pragma unroll
            for (int i = 0; i < 4; i++)
#pragma unroll
                for (int j = 0; j < 4; j++) acc[i][j] = fmaf(a_[i], b_[j], acc[i][j]);
        }
        __syncthreads();
    }
#pragma unroll
    for (int i = 0; i < 4; i++) {
        int rr = row0 + ty * 4 + i;
#pragma unroll
        for (int j = 0; j < 4; j++) {
            int cc = col0 + tx * 4 + j;
            float v = acc[i][j];
            if (ACC) v += C[(size_t)rr * ldc + cc];
            else v += bias[cc];
            if (RELU) v = fmaxf(v, 0.f);
            C[(size_t)rr * ldc + cc] = v;
        }
    }
}

// ---------------- 128x64-tile GEMM, 8x4/thread, K-step 8, double-buffered ----------------
// EPI: 0 = store(acc+bias)[RELU?], 1 = store relu(C+acc), 2 = atomicAdd into g_z2
// K slice: [blockIdx.z * ksz, +ksz)
template <int EPI, bool RELU>
__global__ __launch_bounds__(256) void gemmW_kernel(
    const float* __restrict__ A, int lda,
    const float* __restrict__ B, int Np,
    const float* __restrict__ bias,
    float* __restrict__ C, int ldc,
    int ksz) {
    __shared__ float As[2][8][128];
    __shared__ float Bs[2][8][64];
    int tid = threadIdx.x;
    int tx = tid & 15;
    int ty = tid >> 4;
    int row0 = blockIdx.y * 128;
    int col0 = blockIdx.x * 64;
    int kbase = blockIdx.z * ksz;
    int arow = tid >> 1, ak = (tid & 1) * 4;
    int brow = tid >> 4, bcol4 = (tid & 15) * 4;

    float acc[8][4];
#pragma unroll
    for (int i = 0; i < 8; i++)
#pragma unroll
        for (int j = 0; j < 4; j++) acc[i][j] = 0.f;

    const float* Ap = A + (size_t)(row0 + arow) * lda + kbase + ak;
    {
        float4 av = *(const float4*)Ap;
        As[0][ak + 0][arow] = av.x; As[0][ak + 1][arow] = av.y;
        As[0][ak + 2][arow] = av.z; As[0][ak + 3][arow] = av.w;
        if (tid < 128) {
            float4 bv = *(const float4*)&B[(size_t)(kbase + brow) * Np + col0 + bcol4];
            *(float4*)&Bs[0][brow][bcol4] = bv;
        }
    }
    __syncthreads();
    int nk = ksz / 8;
    for (int t = 0; t < nk; t++) {
        int cur = t & 1, nxt = cur ^ 1;
        if (t + 1 < nk) {
            float4 av = *(const float4*)(Ap + (t + 1) * 8);
            As[nxt][ak + 0][arow] = av.x; As[nxt][ak + 1][arow] = av.y;
            As[nxt][ak + 2][arow] = av.z; As[nxt][ak + 3][arow] = av.w;
            if (tid < 128) {
                float4 bv = *(const float4*)&B[(size_t)(kbase + (t + 1) * 8 + brow) * Np + col0 + bcol4];
                *(float4*)&Bs[nxt][brow][bcol4] = bv;
            }
        }
#pragma unroll
        for (int k = 0; k < 8; k++) {
            float4 a0 = *(const float4*)&As[cur][k][ty * 8];
            float4 a1 = *(const float4*)&As[cur][k][ty * 8 + 4];
            float4 bv = *(const float4*)&Bs[cur][k][tx * 4];
            float a_[8] = {a0.x, a0.y, a0.z, a0.w, a1.x, a1.y, a1.z, a1.w};
            float b_[4] = {bv.x, bv.y, bv.z, bv.w};
#pragma unroll
            for (int i = 0; i < 8; i++)
#pragma unroll
                for (int j = 0; j < 4; j++) acc[i][j] = fmaf(a_[i], b_[j], acc[i][j]);
        }
        __syncthreads();
    }
#pragma unroll
    for (int i = 0; i < 8; i++) {
        int rr = row0 + ty * 8 + i;
#pragma unroll
        for (int j = 0; j < 4; j++) {
            int cc = col0 + tx * 4 + j;
            if (EPI == 0) {
                float v = acc[i][j] + bias[cc];
                if (RELU) v = fmaxf(v, 0.f);
                C[(size_t)rr * ldc + cc] = v;
            } else if (EPI == 1) {
                float v = acc[i][j] + C[(size_t)rr * ldc + cc];
                C[(size_t)rr * ldc + cc] = fmaxf(v, 0.f);
            } else {
                atomicAdd(&g_z2[(size_t)rr * 256 + cc], acc[i][j]);
            }
        }
    }
}

__global__ void out2_kernel(const float* __restrict__ fc2b, const float* __restrict__ ow,
                            const float* __restrict__ ob, float* __restrict__ out) {
    int warp = threadIdx.x >> 5;
    int lane = threadIdx.x & 31;
    int row = blockIdx.x * (blockDim.x >> 5) + warp;
    if (row >= G_GRAPHS) return;
    const float* z = g_z2 + (size_t)row * 256;
    float s = 0.f;
#pragma unroll
    for (int k = 0; k < 8; k++) {
        int c = lane + k * 32;
        float v = fmaxf(z[c] + fc2b[c], 0.f);
        s = fmaf(v, ow[c], s);
    }
#pragma unroll
    for (int o = 16; o; o >>= 1) s += __shfl_down_sync(0xffffffffu, s, o);
    if (lane == 0) out[row] = s + ob[0];
}

extern "C" void kernel_launch(void* const* d_in, const int* in_sizes, int n_in,
                              void* d_out, int out_size) {
    const float* x     = (const float*)d_in[0];
    const void*  eidx  = d_in[1];
    const void*  batch = d_in[2];
    const float* sfp   = (const float*)d_in[3];
    const float* w1a   = (const float*)d_in[4];
    const float* b1a   = (const float*)d_in[5];
    const float* ws_a  = (const float*)d_in[6];
    const float* bs_a  = (const float*)d_in[7];
    const float* ws_b  = (const float*)d_in[8];
    const float* bs_b  = (const float*)d_in[9];
    const float* bn_g  = (const float*)d_in[10];
    const float* bn_b  = (const float*)d_in[11];
    const float* fcg_w = (const float*)d_in[12];
    const float* fcg_b = (const float*)d_in[13];
    const float* fs1_w = (const float*)d_in[14];
    const float* fs1_b = (const float*)d_in[15];
    const float* fs2_w = (const float*)d_in[16];
    const float* fs2_b = (const float*)d_in[17];
    const float* fc1_w = (const float*)d_in[18];
    const float* fc1_b = (const float*)d_in[19];
    const float* fc2_w = (const float*)d_in[20];
    const float* fc2_b = (const float*)d_in[21];
    const float* out_w = (const float*)d_in[22];
    const float* out_b = (const float*)d_in[23];
    float* out = (float*)d_out;

    __half *ha, *hb;
    float *tf, *pooled, *z, *s1, *z1, *statsf;
    cudaGetSymbolAddress((void**)&ha, g_ha);
    cudaGetSymbolAddress((void**)&hb, g_hb);
    cudaGetSymbolAddress((void**)&tf, g_tf);
    cudaGetSymbolAddress((void**)&pooled, g_pooled);
    cudaGetSymbolAddress((void**)&z, g_z);
    cudaGetSymbolAddress((void**)&s1, g_s1);
    cudaGetSymbolAddress((void**)&z1, g_z1);
    cudaGetSymbolAddress((void**)&statsf, g_statsf);

    static cudaStream_t sA = nullptr, sB = nullptr;
    static cudaEvent_t evRoot = nullptr, evA = nullptr, evB = nullptr;
    if (!sA) {
        cudaStreamCreateWithFlags(&sA, cudaStreamNonBlocking);
        cudaStreamCreateWithFlags(&sB, cudaStreamNonBlocking);
        cudaEventCreateWithFlags(&evRoot, cudaEventDisableTiming);
        cudaEventCreateWithFlags(&evA, cudaEventDisableTiming);
        cudaEventCreateWithFlags(&evB, cudaEventDisableTiming);
    }

    const int TB = 256;

    cudaEventRecord(evRoot, 0);
    cudaStreamWaitEvent(sA, evRoot, 0);
    cudaStreamWaitEvent(sB, evRoot, 0);

    // 0: init
    init_kernel<<<(G_GRAPHS * 256 + TB - 1) / TB, TB>>>(eidx, out);

    // Branch B: fs1(1) -> fs2(2) -> fc1_bottom(3, captured by ncu)
    gemm64_kernel<false, true><<<dim3(4, 32), 256, 0, sB>>>(
        sfp, SFD, fs1_w, fs1_b, s1, 256, 512, 256);
    gemm64_kernel<false, true><<<dim3(2, 32), 256, 0, sB>>>(
        s1, 256, fs2_w, fs2_b, z + 128, 128, 256, 256);
    gemmW_kernel<0, false><<<dim3(16, 16), 256, 0, sB>>>(
        z + 128, 256, fc1_w + 128 * 1024, 1024, fc1_b, z1, 1024, 128);
    cudaEventRecord(evB, sB);

    // Branch A: pre-transform
    pre_kernel<<<NBLK_TILE, 256, 0, sA>>>(x, w1a, ha);
    cudaEventRecord(evA, sA);

    // Main: CSR build
    hist_kernel<<<(N_EDGES + TB - 1) / TB, TB>>>(eidx);
    scanA_kernel<<<NBLK_SCAN, 256>>>();
    scanC_kernel<<<NBLK_SCAN, 256>>>();
    scatter_kernel<<<(N_EDGES + TB - 1) / TB, TB>>>(eidx);

    // layers
    cudaStreamWaitEvent(0, evA, 0);
    layer_kernel<true, false><<<NBLK_TILE, 256>>>(ha, nullptr, b1a, ws_b, bs_b,
                                                  nullptr, statsf, nullptr, nullptr,
                                                  hb, nullptr);
    __half* tin = hb;
    __half* tout = ha;
    for (int l = 1; l < 4; l++) {
        layer_kernel<false, false><<<NBLK_TILE, 256>>>(
            tin, ws_a + (l - 1) * D * D, bs_a + (l - 1) * D,
            ws_b + l * D * D, bs_b + l * D,
            statsf + (l - 1) * 64, statsf + l * 64,
            bn_g + (l - 1) * D, bn_b + (l - 1) * D, tout, nullptr);
        __half* tmp = tin; tin = tout; tout = tmp;
    }
    layer_kernel<false, true><<<NBLK_TILE, 256>>>(
        tin, ws_a + 3 * D * D, bs_a + 3 * D,
        ws_b + 4 * D * D, bs_b + 4 * D,
        statsf + 3 * 64, statsf + 4 * 64,
        bn_g + 3 * D, bn_b + 3 * D, nullptr, tf);

    // pooling -> gfeat
    pool_kernel<<<(N_NODES * 8 + TB - 1) / TB, TB>>>(tf, batch, statsf + 4 * 64,
                                                     bn_g + 4 * D, bn_b + 4 * D);
    gemm64_kernel<false, true><<<dim3(2, 32), 256>>>(
        pooled, D, fcg_w, fcg_b, z, 128, 32, 256);

    // join solvent branch; fc1_top ; fc2 split-K (z-dim = K slice) ; out
    cudaStreamWaitEvent(0, evB, 0);
    gemmW_kernel<1, true><<<dim3(16, 16), 256>>>(
        z, 256, fc1_w, 1024, nullptr, z1, 1024, 128);
    gemmW_kernel<2, false><<<dim3(4, 16, 4), 256>>>(
        z1, 1024, fc2_w, 256, nullptr, nullptr, 256, 256);
    out2_kernel<<<G_GRAPHS / 8, 256>>>(fc2_b, out_w, out_b, out);
}

// round 13
// speedup vs baseline: 1.2267x; 1.0802x over previous
#include <cuda_runtime.h>
#include <cuda_fp16.h>
#include <mma.h>
#include <cstdint>

using namespace nvcuda;

#define N_NODES 100000
#define N_EDGES 1600000
#define G_GRAPHS 2048
#define NFEAT 64
#define D 32
#define SFD 512
#define BN_EPS 1e-5f
#define NBLK_SCAN 391
#define NTILE 128
#define NBLK_TILE 782

__device__ __half g_ha[N_NODES * D];
__device__ __half g_hb[N_NODES * D];
__device__ float  g_tf[N_NODES * D];
__device__ float  g_statsf[5 * 64];
__device__ float  g_pooled[G_GRAPHS * D];
__device__ __half g_zh[G_GRAPHS * 256];      // concat [gfeat | solvent], fp16
__device__ float  g_s1[G_GRAPHS * 256];
__device__ float  g_z1[G_GRAPHS * 1024];
__device__ __half g_z1h[G_GRAPHS * 1024];
__device__ float  g_z2[G_GRAPHS * 256];
__device__ __half g_fc1wh[256 * 1024];
__device__ __half g_fc2wh[1024 * 256];
__device__ int    g_is64;
__device__ int    g_rowptr[N_NODES + 1];
__device__ int    g_cnt[N_NODES];
__device__ int    g_col[N_EDGES];
__device__ int    g_bsum[NBLK_SCAN];

__device__ __forceinline__ int load_idx(const void* p, long i, int is64) {
    if (is64) return (int)((const long long*)p)[i];
    return ((const int*)p)[i];
}

__device__ __forceinline__ void redf(float* p, float v) {
    asm volatile("red.global.add.f32 [%0], %1;" :: "l"(p), "f"(v) : "memory");
}

__global__ void init_kernel(const void* edge, float* out) {
    int i = blockIdx.x * blockDim.x + threadIdx.x;
    if (i < N_NODES) g_cnt[i] = 0;
    if (i < G_GRAPHS * D) g_pooled[i] = 0.f;
    if (i < 5 * 64) g_statsf[i] = 0.f;
    if (i < G_GRAPHS) out[i] = 0.f;
    if (i == 0) {
        const unsigned long long* p = (const unsigned long long*)edge;
        int is64 = 1;
        for (int k = 0; k < 8; k++)
            if (p[k] >= (unsigned long long)N_NODES) is64 = 0;
        g_is64 = is64;
    }
}

// convert fc1_w and fc2_w to fp16
__global__ void convW_kernel(const float* __restrict__ w1, const float* __restrict__ w2) {
    int i = blockIdx.x * blockDim.x + threadIdx.x;
    if (i < 256 * 1024) g_fc1wh[i] = __float2half(w1[i]);
    if (i < 1024 * 256) g_fc2wh[i] = __float2half(w2[i]);
}

__global__ void hist_kernel(const void* __restrict__ eidx) {
    int e = blockIdx.x * blockDim.x + threadIdx.x;
    if (e >= N_EDGES) return;
    int d = load_idx(eidx, (long)N_EDGES + e, g_is64);
    atomicAdd(&g_cnt[d], 1);
}

__global__ void scanA_kernel() {
    __shared__ int sh[256];
    int i = blockIdx.x * 256 + threadIdx.x;
    int v = (i < N_NODES) ? g_cnt[i] : 0;
    sh[threadIdx.x] = v;
    __syncthreads();
    for (int off = 128; off; off >>= 1) {
        if (threadIdx.x < off) sh[threadIdx.x] += sh[threadIdx.x + off];
        __syncthreads();
    }
    if (threadIdx.x == 0) g_bsum[blockIdx.x] = sh[0];
}

__global__ void scanC_kernel() {
    __shared__ int sbase[256];
    __shared__ int sh[256];
    int t = threadIdx.x;
    int b = blockIdx.x;
    int v = 0;
    for (int k = t; k < b; k += 256) v += g_bsum[k];
    sbase[t] = v;
    __syncthreads();
    for (int off = 128; off; off >>= 1) {
        if (t < off) sbase[t] += sbase[t + off];
        __syncthreads();
    }
    int base = sbase[0];
    int i = b * 256 + t;
    int c = (i < N_NODES) ? g_cnt[i] : 0;
    sh[t] = c;
    __syncthreads();
    for (int off = 1; off < 256; off <<= 1) {
        int a = (t >= off) ? sh[t - off] : 0;
        __syncthreads();
        sh[t] += a;
        __syncthreads();
    }
    if (i < N_NODES) {
        g_rowptr[i + 1] = base + sh[t];
        g_cnt[i] = 0;
    }
    if (i == 0) g_rowptr[0] = 0;
}

__global__ void scatter_kernel(const void* __restrict__ eidx) {
    int e = blockIdx.x * blockDim.x + threadIdx.x;
    if (e >= N_EDGES) return;
    int is64 = g_is64;
    int s = load_idx(eidx, e, is64);
    int d = load_idx(eidx, (long)N_EDGES + e, is64);
    int pos = g_rowptr[d] + atomicAdd(&g_cnt[d], 1);
    g_col[pos] = s;
}

__global__ __launch_bounds__(256) void pre_kernel(const float* __restrict__ x,
                                                  const float* __restrict__ w1a,
                                                  __half* __restrict__ u) {
    __shared__ float sX[NTILE * 68];
    __shared__ float sW[NFEAT * D];
    for (int i = threadIdx.x; i < NFEAT * D; i += 256) sW[i] = w1a[i];
    int base = blockIdx.x * NTILE;
    for (int i = threadIdx.x; i < NTILE * 16; i += 256) {
        int n = i >> 4, k4 = i & 15;
        int node = base + n;
        float4 v = make_float4(0.f, 0.f, 0.f, 0.f);
        if (node < N_NODES) v = ((const float4*)x)[(size_t)node * 16 + k4];
        *(float4*)&sX[n * 68 + k4 * 4] = v;
    }
    __syncthreads();
    int j0 = (threadIdx.x & 7) * 4;
    int n0 = (threadIdx.x >> 3) * 4;
    float acc[4][4];
#pragma unroll
    for (int i = 0; i < 4; i++)
#pragma unroll
        for (int j = 0; j < 4; j++) acc[i][j] = 0.f;
#pragma unroll 8
    for (int k = 0; k < NFEAT; k++) {
        float a0 = sX[(n0 + 0) * 68 + k];
        float a1 = sX[(n0 + 1) * 68 + k];
        float a2 = sX[(n0 + 2) * 68 + k];
        float a3 = sX[(n0 + 3) * 68 + k];
        float4 w = *(const float4*)&sW[k * D + j0];
        acc[0][0] = fmaf(a0, w.x, acc[0][0]); acc[0][1] = fmaf(a0, w.y, acc[0][1]);
        acc[0][2] = fmaf(a0, w.z, acc[0][2]); acc[0][3] = fmaf(a0, w.w, acc[0][3]);
        acc[1][0] = fmaf(a1, w.x, acc[1][0]); acc[1][1] = fmaf(a1, w.y, acc[1][1]);
        acc[1][2] = fmaf(a1, w.z, acc[1][2]); acc[1][3] = fmaf(a1, w.w, acc[1][3]);
        acc[2][0] = fmaf(a2, w.x, acc[2][0]); acc[2][1] = fmaf(a2, w.y, acc[2][1]);
        acc[2][2] = fmaf(a2, w.z, acc[2][2]); acc[2][3] = fmaf(a2, w.w, acc[2][3]);
        acc[3][0] = fmaf(a3, w.x, acc[3][0]); acc[3][1] = fmaf(a3, w.y, acc[3][1]);
        acc[3][2] = fmaf(a3, w.z, acc[3][2]); acc[3][3] = fmaf(a3, w.w, acc[3][3]);
    }
    __half2* u2 = (__half2*)u;
#pragma unroll
    for (int i = 0; i < 4; i++) {
        int node = base + n0 + i;
        if (node < N_NODES) {
            u2[(size_t)node * 16 + (j0 >> 1)] = __floats2half2_rn(acc[i][0], acc[i][1]);
            u2[(size_t)node * 16 + (j0 >> 1) + 1] = __floats2half2_rn(acc[i][2], acc[i][3]);
        }
    }
}

template <bool FIRST, bool OUTF32>
__global__ __launch_bounds__(256, 4) void layer_kernel(
    const __half* __restrict__ tin, const float* __restrict__ Wa,
    const float* __restrict__ ba, const float* __restrict__ Wb,
    const float* __restrict__ bb,
    const float* __restrict__ stats_in, float* __restrict__ stats_out,
    const float* __restrict__ bng, const float* __restrict__ bnb,
    __half* __restrict__ tout16, float* __restrict__ toutf) {
    __shared__ float sA[NTILE * 34];
    __shared__ float sWa[D * D];
    __shared__ float sWb[D * D];
    __shared__ float sba[D], sbb[D];
    __shared__ float sstat[64];
    int tid = threadIdx.x;
    if (!FIRST)
        for (int i = tid; i < D * D; i += 256) sWa[i] = Wa[i];
    for (int i = tid; i < D * D; i += 256) sWb[i] = Wb[i];
    if (tid < D) { sba[tid] = ba[tid]; sbb[tid] = bb[tid]; }
    if (tid < 64) sstat[tid] = 0.f;
    int lane = tid & 31, warp = tid >> 5;
    int f2 = lane & 15;
    int side = lane >> 4;
    float scx = 0.f, shx = 0.f, scy = 0.f, shy = 0.f;
    if (!FIRST) {
        int fx = 2 * f2, fy = 2 * f2 + 1;
        float Sx = stats_in[fx], Qx = stats_in[D + fx];
        float mux = Sx * (1.f / N_NODES);
        float vax = Qx * (1.f / N_NODES) - mux * mux;
        scx = rsqrtf(vax + BN_EPS) * bng[fx];
        shx = bnb[fx] - mux * scx;
        float Sy = stats_in[fy], Qy = stats_in[D + fy];
        float muy = Sy * (1.f / N_NODES);
        float vay = Qy * (1.f / N_NODES) - muy * muy;
        scy = rsqrtf(vay + BN_EPS) * bng[fy];
        shy = bnb[fy] - muy * scy;
    }
    __syncthreads();

    const __half2* tin2 = (const __half2*)tin;
    int base = blockIdx.x * NTILE;

    for (int r = 0; r < 16; r++) {
        int nl = warp * 16 + r;
        int node = base + nl;
        float ax = 0.f, ay = 0.f;
        if (node < N_NODES) {
            if (side == 0) {
                float2 v = __half22float2(tin2[(size_t)node * 16 + f2]);
                if (!FIRST) {
                    v.x = fmaxf(fmaf(v.x, scx, shx), 0.f);
                    v.y = fmaxf(fmaf(v.y, scy, shy), 0.f);
                }
                ax += v.x; ay += v.y;
            }
            int r0 = g_rowptr[node], r1 = g_rowptr[node + 1];
            for (int i = r0; i < r1; i += 16) {
                int cc[8];
                bool vb[8];
#pragma unroll
                for (int k = 0; k < 8; k++) {
                    int idx = i + 2 * k + side;
                    vb[k] = idx < r1;
                    cc[k] = g_col[vb[k] ? idx : (r1 - 1)];
                }
                float2 vv[8];
#pragma unroll
                for (int k = 0; k < 8; k++)
                    vv[k] = __half22float2(tin2[(size_t)cc[k] * 16 + f2]);
#pragma unroll
                for (int k = 0; k < 8; k++) {
                    if (vb[k]) {
                        float vx = vv[k].x, vy = vv[k].y;
                        if (!FIRST) {
                            vx = fmaxf(fmaf(vx, scx, shx), 0.f);
                            vy = fmaxf(fmaf(vy, scy, shy), 0.f);
                        }
                        ax += vx; ay += vy;
                    }
                }
            }
        }
        ax += __shfl_xor_sync(0xffffffffu, ax, 16);
        ay += __shfl_xor_sync(0xffffffffu, ay, 16);
        if (side == 0) {
            if (FIRST) {
                ax = fmaxf(ax + sba[2 * f2], 0.f);
                ay = fmaxf(ay + sba[2 * f2 + 1], 0.f);
            }
            *(float2*)&sA[nl * 34 + 2 * f2] = make_float2(ax, ay);
        }
    }
    __syncthreads();

    int j0 = (tid & 7) * 4;
    int n0 = (tid >> 3) * 4;

    if (!FIRST) {
        float acc[4][4];
#pragma unroll
        for (int i = 0; i < 4; i++)
#pragma unroll
            for (int j = 0; j < 4; j++) acc[i][j] = 0.f;
#pragma unroll
        for (int k = 0; k < D; k++) {
            float a0 = sA[(n0 + 0) * 34 + k];
            float a1 = sA[(n0 + 1) * 34 + k];
            float a2 = sA[(n0 + 2) * 34 + k];
            float a3 = sA[(n0 + 3) * 34 + k];
            float4 w = *(const float4*)&sWa[k * D + j0];
            acc[0][0] = fmaf(a0, w.x, acc[0][0]); acc[0][1] = fmaf(a0, w.y, acc[0][1]);
            acc[0][2] = fmaf(a0, w.z, acc[0][2]); acc[0][3] = fmaf(a0, w.w, acc[0][3]);
            acc[1][0] = fmaf(a1, w.x, acc[1][0]); acc[1][1] = fmaf(a1, w.y, acc[1][1]);
            acc[1][2] = fmaf(a1, w.z, acc[1][2]); acc[1][3] = fmaf(a1, w.w, acc[1][3]);
            acc[2][0] = fmaf(a2, w.x, acc[2][0]); acc[2][1] = fmaf(a2, w.y, acc[2][1]);
            acc[2][2] = fmaf(a2, w.z, acc[2][2]); acc[2][3] = fmaf(a2, w.w, acc[2][3]);
            acc[3][0] = fmaf(a3, w.x, acc[3][0]); acc[3][1] = fmaf(a3, w.y, acc[3][1]);
            acc[3][2] = fmaf(a3, w.z, acc[3][2]); acc[3][3] = fmaf(a3, w.w, acc[3][3]);
        }
        __syncthreads();
#pragma unroll
        for (int i = 0; i < 4; i++)
#pragma unroll
            for (int j = 0; j < 4; j++)
                sA[(n0 + i) * 34 + j0 + j] = fmaxf(acc[i][j] + sba[j0 + j], 0.f);
        __syncthreads();
    }

    float acc2[4][4];
#pragma unroll
    for (int i = 0; i < 4; i++)
#pragma unroll
        for (int j = 0; j < 4; j++) acc2[i][j] = 0.f;
#pragma unroll
    for (int k = 0; k < D; k++) {
        float a0 = sA[(n0 + 0) * 34 + k];
        float a1 = sA[(n0 + 1) * 34 + k];
        float a2 = sA[(n0 + 2) * 34 + k];
        float a3 = sA[(n0 + 3) * 34 + k];
        float4 w = *(const float4*)&sWb[k * D + j0];
        acc2[0][0] = fmaf(a0, w.x, acc2[0][0]); acc2[0][1] = fmaf(a0, w.y, acc2[0][1]);
        acc2[0][2] = fmaf(a0, w.z, acc2[0][2]); acc2[0][3] = fmaf(a0, w.w, acc2[0][3]);
        acc2[1][0] = fmaf(a1, w.x, acc2[1][0]); acc2[1][1] = fmaf(a1, w.y, acc2[1][1]);
        acc2[1][2] = fmaf(a1, w.z, acc2[1][2]); acc2[1][3] = fmaf(a1, w.w, acc2[1][3]);
        acc2[2][0] = fmaf(a2, w.x, acc2[2][0]); acc2[2][1] = fmaf(a2, w.y, acc2[2][1]);
        acc2[2][2] = fmaf(a2, w.z, acc2[2][2]); acc2[2][3] = fmaf(a2, w.w, acc2[2][3]);
        acc2[3][0] = fmaf(a3, w.x, acc2[3][0]); acc2[3][1] = fmaf(a3, w.y, acc2[3][1]);
        acc2[3][2] = fmaf(a3, w.z, acc2[3][2]); acc2[3][3] = fmaf(a3, w.w, acc2[3][3]);
    }
    float colS[4] = {0.f, 0.f, 0.f, 0.f};
    float colQ[4] = {0.f, 0.f, 0.f, 0.f};
    __half2* t2 = (__half2*)tout16;
#pragma unroll
    for (int i = 0; i < 4; i++) {
        int node = base + n0 + i;
        if (node < N_NODES) {
            float z0 = acc2[i][0] + sbb[j0 + 0];
            float z1 = acc2[i][1] + sbb[j0 + 1];
            float z2 = acc2[i][2] + sbb[j0 + 2];
            float z3 = acc2[i][3] + sbb[j0 + 3];
            if (OUTF32) {
                *(float4*)&toutf[(size_t)node * D + j0] = make_float4(z0, z1, z2, z3);
            } else {
                t2[(size_t)node * 16 + (j0 >> 1)] = __floats2half2_rn(z0, z1);
                t2[(size_t)node * 16 + (j0 >> 1) + 1] = __floats2half2_rn(z2, z3);
            }
            colS[0] += z0; colS[1] += z1; colS[2] += z2; colS[3] += z3;
            colQ[0] += z0 * z0; colQ[1] += z1 * z1; colQ[2] += z2 * z2; colQ[3] += z3 * z3;
        }
    }
#pragma unroll
    for (int j = 0; j < 4; j++) {
        atomicAdd(&sstat[j0 + j], colS[j]);
        atomicAdd(&sstat[32 + j0 + j], colQ[j]);
    }
    __syncthreads();
    if (tid < 64) redf(&stats_out[tid], sstat[tid]);
}

__global__ __launch_bounds__(256) void pool_kernel(const float* __restrict__ t,
                                                   const void* __restrict__ batch,
                                                   const float* __restrict__ stats,
                                                   const float* __restrict__ bng,
                                                   const float* __restrict__ bnb) {
    __shared__ float ssc[D], ssh[D];
    if (threadIdx.x < D) {
        int f = threadIdx.x;
        float S = stats[f], Q = stats[D + f];
        float mu = S * (1.f / N_NODES);
        float var = Q * (1.f / N_NODES) - mu * mu;
        float rs = rsqrtf(var + BN_EPS);
        float sc = rs * bng[f];
        ssc[f] = sc;
        ssh[f] = bnb[f] - mu * sc;
    }
    __syncthreads();
    int i = blockIdx.x * blockDim.x + threadIdx.x;
    if (i >= N_NODES * (D / 4)) return;
    int node = i >> 3;
    int j = i & 7;
    int b = load_idx(batch, node, g_is64);
    float4 v = ((const float4*)t)[i];
    float4 o;
    o.x = fmaxf(fmaf(v.x, ssc[j * 4 + 0], ssh[j * 4 + 0]), 0.f);
    o.y = fmaxf(fmaf(v.y, ssc[j * 4 + 1], ssh[j * 4 + 1]), 0.f);
    o.z = fmaxf(fmaf(v.z, ssc[j * 4 + 2], ssh[j * 4 + 2]), 0.f);
    o.w = fmaxf(fmaf(v.w, ssc[j * 4 + 3], ssh[j * 4 + 3]), 0.f);
    float* p = g_pooled + (size_t)b * D + j * 4;
    asm volatile("red.global.add.v4.f32 [%0], {%1,%2,%3,%4};"
                 :: "l"(p), "f"(o.x), "f"(o.y), "f"(o.z), "f"(o.w) : "memory");
}

// ---------------- fp32 64x64 GEMM; OUTH: write fp16 ----------------
template <bool RELU, bool OUTH>
__global__ __launch_bounds__(256) void gemm64_kernel(
    const float* __restrict__ A, int lda,
    const float* __restrict__ B,
    const float* __restrict__ bias,
    float* __restrict__ C, __half* __restrict__ Ch,
    int Np, int K, int ldc) {
    __shared__ float As[16][64];
    __shared__ float Bs[16][64];
    int tid = threadIdx.x;
    int tx = tid & 15;
    int ty = tid >> 4;
    int row0 = blockIdx.y * 64;
    int col0 = blockIdx.x * 64;
    float acc[4][4];
#pragma unroll
    for (int i = 0; i < 4; i++)
#pragma unroll
        for (int j = 0; j < 4; j++) acc[i][j] = 0.f;

    for (int kt = 0; kt < K; kt += 16) {
#pragma unroll
        for (int r = 0; r < 4; r++) {
            int idx = tid + r * 256;
            int m = idx >> 4, k = idx & 15;
            As[k][m] = A[(size_t)(row0 + m) * lda + kt + k];
            int bk = idx >> 6, c = idx & 63;
            Bs[bk][c] = B[(size_t)(kt + bk) * Np + col0 + c];
        }
        __syncthreads();
#pragma unroll
        for (int k = 0; k < 16; k++) {
            float4 av = *(const float4*)&As[k][ty * 4];
            float4 bv = *(const float4*)&Bs[k][tx * 4];
            float a_[4] = {av.x, av.y, av.z, av.w};
            float b_[4] = {bv.x, bv.y, bv.z, bv.w};
#pragma unroll
            for (int i = 0; i < 4; i++)
#pragma unroll
                for (int j = 0; j < 4; j++) acc[i][j] = fmaf(a_[i], b_[j], acc[i][j]);
        }
        __syncthreads();
    }
#pragma unroll
    for (int i = 0; i < 4; i++) {
        int rr = row0 + ty * 4 + i;
#pragma unroll
        for (int j = 0; j < 4; j++) {
            int cc = col0 + tx * 4 + j;
            float v = acc[i][j] + bias[cc];
            if (RELU) v = fmaxf(v, 0.f);
            if (OUTH) Ch[(size_t)rr * ldc + cc] = __float2half(v);
            else C[(size_t)rr * ldc + cc] = v;
        }
    }
}

// ---------------- wmma fp16 GEMM, 64x64 tile, 8 warps ----------------
// EPI 0: C = acc + bias            (fc1_bottom; no relu)
// EPI 1: v = relu(acc + C); C = v; Ch = half(v)   (fc1_top)
// EPI 2: C = acc                   (fc2 -> z2)
template <int EPI>
__global__ __launch_bounds__(256) void wgemm_kernel(
    const __half* __restrict__ A, int lda,
    const __half* __restrict__ B, int ldb,
    const float* __restrict__ bias,
    float* __restrict__ C, int ldc,
    __half* __restrict__ Ch, int K) {
    __shared__ __half As[64][24];
    __shared__ __half Bs[16][72];
    __shared__ float Cs[64][68];
    int tid = threadIdx.x;
    int warp = tid >> 5;
    int wy = warp >> 1, wx = warp & 1;
    int row0 = blockIdx.y * 64;
    int col0 = blockIdx.x * 64;

    wmma::fragment<wmma::accumulator, 16, 16, 16, float> acc0, acc1;
    wmma::fill_fragment(acc0, 0.f);
    wmma::fill_fragment(acc1, 0.f);

    int arow = tid >> 2, acol = (tid & 3) * 4;    // 64 x 16 tile, 4 halves/thread
    int brow = tid >> 4, bcol = (tid & 15) * 4;   // 16 x 64 tile

    for (int kt = 0; kt < K; kt += 16) {
        *(uint2*)&As[arow][acol] = *(const uint2*)&A[(size_t)(row0 + arow) * lda + kt + acol];
        *(uint2*)&Bs[brow][bcol] = *(const uint2*)&B[(size_t)(kt + brow) * ldb + col0 + bcol];
        __syncthreads();
        wmma::fragment<wmma::matrix_a, 16, 16, 16, __half, wmma::row_major> af;
        wmma::fragment<wmma::matrix_b, 16, 16, 16, __half, wmma::row_major> bf0, bf1;
        wmma::load_matrix_sync(af, &As[wy * 16][0], 24);
        wmma::load_matrix_sync(bf0, &Bs[0][wx * 32], 72);
        wmma::load_matrix_sync(bf1, &Bs[0][wx * 32 + 16], 72);
        wmma::mma_sync(acc0, af, bf0, acc0);
        wmma::mma_sync(acc1, af, bf1, acc1);
        __syncthreads();
    }
    wmma::store_matrix_sync(&Cs[wy * 16][wx * 32], acc0, 68, wmma::mem_row_major);
    wmma::store_matrix_sync(&Cs[wy * 16][wx * 32 + 16], acc1, 68, wmma::mem_row_major);
    __syncthreads();
    for (int i = tid; i < 64 * 64; i += 256) {
        int r = i >> 6, c = i & 63;
        int rr = row0 + r, cc = col0 + c;
        float v = Cs[r][c];
        if (EPI == 0) {
            C[(size_t)rr * ldc + cc] = v + bias[cc];
        } else if (EPI == 1) {
            v += C[(size_t)rr * ldc + cc];
            v = fmaxf(v, 0.f);
            Ch[(size_t)rr * ldc + cc] = __float2half(v);
        } else {
            C[(size_t)rr * ldc + cc] = v;
        }
    }
}

__global__ void out2_kernel(const float* __restrict__ fc2b, const float* __restrict__ ow,
                            const float* __restrict__ ob, float* __restrict__ out) {
    int warp = threadIdx.x >> 5;
    int lane = threadIdx.x & 31;
    int row = blockIdx.x * (blockDim.x >> 5) + warp;
    if (row >= G_GRAPHS) return;
    const float* z = g_z2 + (size_t)row * 256;
    float s = 0.f;
#pragma unroll
    for (int k = 0; k < 8; k++) {
        int c = lane + k * 32;
        float v = fmaxf(z[c] + fc2b[c], 0.f);
        s = fmaf(v, ow[c], s);
    }
#pragma unroll
    for (int o = 16; o; o >>= 1) s += __shfl_down_sync(0xffffffffu, s, o);
    if (lane == 0) out[row] = s + ob[0];
}

extern "C" void kernel_launch(void* const* d_in, const int* in_sizes, int n_in,
                              void* d_out, int out_size) {
    const float* x     = (const float*)d_in[0];
    const void*  eidx  = d_in[1];
    const void*  batch = d_in[2];
    const float* sfp   = (const float*)d_in[3];
    const float* w1a   = (const float*)d_in[4];
    const float* b1a   = (const float*)d_in[5];
    const float* ws_a  = (const float*)d_in[6];
    const float* bs_a  = (const float*)d_in[7];
    const float* ws_b  = (const float*)d_in[8];
    const float* bs_b  = (const float*)d_in[9];
    const float* bn_g  = (const float*)d_in[10];
    const float* bn_b  = (const float*)d_in[11];
    const float* fcg_w = (const float*)d_in[12];
    const float* fcg_b = (const float*)d_in[13];
    const float* fs1_w = (const float*)d_in[14];
    const float* fs1_b = (const float*)d_in[15];
    const float* fs2_w = (const float*)d_in[16];
    const float* fs2_b = (const float*)d_in[17];
    const float* fc1_w = (const float*)d_in[18];
    const float* fc1_b = (const float*)d_in[19];
    const float* fc2_w = (const float*)d_in[20];
    const float* fc2_b = (const float*)d_in[21];
    const float* out_w = (const float*)d_in[22];
    const float* out_b = (const float*)d_in[23];
    float* out = (float*)d_out;

    __half *ha, *hb, *zh, *z1h, *fc1wh, *fc2wh;
    float *tf, *pooled, *s1, *z1, *z2, *statsf;
    cudaGetSymbolAddress((void**)&ha, g_ha);
    cudaGetSymbolAddress((void**)&hb, g_hb);
    cudaGetSymbolAddress((void**)&zh, g_zh);
    cudaGetSymbolAddress((void**)&z1h, g_z1h);
    cudaGetSymbolAddress((void**)&fc1wh, g_fc1wh);
    cudaGetSymbolAddress((void**)&fc2wh, g_fc2wh);
    cudaGetSymbolAddress((void**)&tf, g_tf);
    cudaGetSymbolAddress((void**)&pooled, g_pooled);
    cudaGetSymbolAddress((void**)&s1, g_s1);
    cudaGetSymbolAddress((void**)&z1, g_z1);
    cudaGetSymbolAddress((void**)&z2, g_z2);
    cudaGetSymbolAddress((void**)&statsf, g_statsf);

    static cudaStream_t sA = nullptr, sB = nullptr;
    static cudaEvent_t evRoot = nullptr, evA = nullptr, evB = nullptr;
    if (!sA) {
        cudaStreamCreateWithFlags(&sA, cudaStreamNonBlocking);
        cudaStreamCreateWithFlags(&sB, cudaStreamNonBlocking);
        cudaEventCreateWithFlags(&evRoot, cudaEventDisableTiming);
        cudaEventCreateWithFlags(&evA, cudaEventDisableTiming);
        cudaEventCreateWithFlags(&evB, cudaEventDisableTiming);
    }

    const int TB = 256;

    cudaEventRecord(evRoot, 0);
    cudaStreamWaitEvent(sA, evRoot, 0);
    cudaStreamWaitEvent(sB, evRoot, 0);

    // 0: init
    init_kernel<<<(N_NODES + TB - 1) / TB, TB>>>(eidx, out);

    // Branch B: weight convert(1) -> fs1(2) -> fs2(3) -> fc1_bottom(4)
    convW_kernel<<<(256 * 1024 + TB - 1) / TB, TB, 0, sB>>>(fc1_w, fc2_w);
    gemm64_kernel<true, false><<<dim3(4, 32), 256, 0, sB>>>(
        sfp, SFD, fs1_w, fs1_b, s1, nullptr, 256, 512, 256);
    gemm64_kernel<true, true><<<dim3(2, 32), 256, 0, sB>>>(
        s1, 256, fs2_w, fs2_b, nullptr, zh + 128, 128, 256, 256);
    wgemm_kernel<0><<<dim3(16, 32), 256, 0, sB>>>(
        zh + 128, 256, fc1wh + 128 * 1024, 1024, fc1_b, z1, 1024, nullptr, 128);
    cudaEventRecord(evB, sB);

    // Branch A: pre-transform
    pre_kernel<<<NBLK_TILE, 256, 0, sA>>>(x, w1a, ha);
    cudaEventRecord(evA, sA);

    // Main: CSR build
    hist_kernel<<<(N_EDGES + TB - 1) / TB, TB>>>(eidx);
    scanA_kernel<<<NBLK_SCAN, 256>>>();
    scanC_kernel<<<NBLK_SCAN, 256>>>();
    scatter_kernel<<<(N_EDGES + TB - 1) / TB, TB>>>(eidx);

    // layers
    cudaStreamWaitEvent(0, evA, 0);
    layer_kernel<true, false><<<NBLK_TILE, 256>>>(ha, nullptr, b1a, ws_b, bs_b,
                                                  nullptr, statsf, nullptr, nullptr,
                                                  hb, nullptr);
    __half* tin = hb;
    __half* tout = ha;
    for (int l = 1; l < 4; l++) {
        layer_kernel<false, false><<<NBLK_TILE, 256>>>(
            tin, ws_a + (l - 1) * D * D, bs_a + (l - 1) * D,
            ws_b + l * D * D, bs_b + l * D,
            statsf + (l - 1) * 64, statsf + l * 64,
            bn_g + (l - 1) * D, bn_b + (l - 1) * D, tout, nullptr);
        __half* tmp = tin; tin = tout; tout = tmp;
    }
    layer_kernel<false, true><<<NBLK_TILE, 256>>>(
        tin, ws_a + 3 * D * D, bs_a + 3 * D,
        ws_b + 4 * D * D, bs_b + 4 * D,
        statsf + 3 * 64, statsf + 4 * 64,
        bn_g + 3 * D, bn_b + 3 * D, nullptr, tf);

    // pooling -> gfeat (fp16 out into left half of zh)
    pool_kernel<<<(N_NODES * 8 + TB - 1) / TB, TB>>>(tf, batch, statsf + 4 * 64,
                                                     bn_g + 4 * D, bn_b + 4 * D);
    gemm64_kernel<true, true><<<dim3(2, 32), 256>>>(
        pooled, D, fcg_w, fcg_b, nullptr, zh, 128, 32, 256);

    // join solvent branch; fc1_top (wmma, acc+relu -> z1h) ; fc2 (wmma -> z2) ; out
    cudaStreamWaitEvent(0, evB, 0);
    wgemm_kernel<1><<<dim3(16, 32), 256>>>(
        zh, 256, fc1wh, 1024, nullptr, z1, 1024, z1h, 128);
    wgemm_kernel<2><<<dim3(4, 32), 256>>>(
        z1h, 1024, fc2wh, 256, nullptr, z2, 256, nullptr, 1024);
    out2_kernel<<<G_GRAPHS / 8, 256>>>(fc2_b, out_w, out_b, out);
}

// round 14
// speedup vs baseline: 1.2504x; 1.0193x over previous
#include <cuda_runtime.h>
#include <cuda_fp16.h>
#include <mma.h>
#include <cstdint>

using namespace nvcuda;

#define N_NODES 100000
#define N_EDGES 1600000
#define G_GRAPHS 2048
#define NFEAT 64
#define D 32
#define SFD 512
#define BN_EPS 1e-5f
#define NBLK_SCAN 391
#define NTILE 128
#define NBLK_TILE 782

__device__ __half g_ha[N_NODES * D];
__device__ __half g_hb[N_NODES * D];
__device__ float  g_tf[N_NODES * D];
__device__ float  g_statsf[5 * 64];
__device__ float  g_pooled[G_GRAPHS * D];
__device__ __half g_pooledh[G_GRAPHS * D];
__device__ __half g_zh[G_GRAPHS * 256];      // concat [gfeat | solvent], fp16
__device__ __half g_sfph[G_GRAPHS * SFD];
__device__ __half g_s1h[G_GRAPHS * 256];
__device__ float  g_z1[G_GRAPHS * 1024];
__device__ __half g_z1h[G_GRAPHS * 1024];
__device__ __half g_fc1wh[256 * 1024];
__device__ __half g_fc2wh[1024 * 256];
__device__ __half g_fs1wh[SFD * 256];
__device__ __half g_fs2wh[256 * 128];
__device__ __half g_fcgwh[D * 128];
__device__ int    g_is64;
__device__ int    g_rowptr[N_NODES + 1];
__device__ int    g_cnt[N_NODES];
__device__ int    g_col[N_EDGES];
__device__ int    g_bsum[NBLK_SCAN];

__device__ __forceinline__ int load_idx(const void* p, long i, int is64) {
    if (is64) return (int)((const long long*)p)[i];
    return ((const int*)p)[i];
}

__device__ __forceinline__ void redf(float* p, float v) {
    asm volatile("red.global.add.f32 [%0], %1;" :: "l"(p), "f"(v) : "memory");
}

__global__ void init_kernel(const void* edge, float* out) {
    int i = blockIdx.x * blockDim.x + threadIdx.x;
    if (i < N_NODES) g_cnt[i] = 0;
    if (i < G_GRAPHS * D) g_pooled[i] = 0.f;
    if (i < 5 * 64) g_statsf[i] = 0.f;
    if (i < G_GRAPHS) out[i] = 0.f;
    if (i == 0) {
        const unsigned long long* p = (const unsigned long long*)edge;
        int is64 = 1;
        for (int k = 0; k < 8; k++)
            if (p[k] >= (unsigned long long)N_NODES) is64 = 0;
        g_is64 = is64;
    }
}

// convert head weights to fp16
__global__ void convW_kernel(const float* __restrict__ w1, const float* __restrict__ w2,
                             const float* __restrict__ wf1, const float* __restrict__ wf2,
                             const float* __restrict__ wg) {
    int i = blockIdx.x * blockDim.x + threadIdx.x;
    if (i < 256 * 1024) g_fc1wh[i] = __float2half(w1[i]);
    if (i < 1024 * 256) g_fc2wh[i] = __float2half(w2[i]);
    if (i < SFD * 256) g_fs1wh[i] = __float2half(wf1[i]);
    if (i < 256 * 128) g_fs2wh[i] = __float2half(wf2[i]);
    if (i < D * 128) g_fcgwh[i] = __float2half(wg[i]);
}

// convert solvent fingerprints to fp16
__global__ void convS_kernel(const float* __restrict__ sfp) {
    int i = blockIdx.x * blockDim.x + threadIdx.x;
    if (i < G_GRAPHS * SFD) g_sfph[i] = __float2half(sfp[i]);
}

// pooled -> fp16
__global__ void pconv_kernel() {
    int i = blockIdx.x * blockDim.x + threadIdx.x;
    if (i < G_GRAPHS * D) g_pooledh[i] = __float2half(g_pooled[i]);
}

__global__ void hist_kernel(const void* __restrict__ eidx) {
    int e = blockIdx.x * blockDim.x + threadIdx.x;
    if (e >= N_EDGES) return;
    int d = load_idx(eidx, (long)N_EDGES + e, g_is64);
    atomicAdd(&g_cnt[d], 1);
}

__global__ void scanA_kernel() {
    __shared__ int sh[256];
    int i = blockIdx.x * 256 + threadIdx.x;
    int v = (i < N_NODES) ? g_cnt[i] : 0;
    sh[threadIdx.x] = v;
    __syncthreads();
    for (int off = 128; off; off >>= 1) {
        if (threadIdx.x < off) sh[threadIdx.x] += sh[threadIdx.x + off];
        __syncthreads();
    }
    if (threadIdx.x == 0) g_bsum[blockIdx.x] = sh[0];
}

__global__ void scanC_kernel() {
    __shared__ int sbase[256];
    __shared__ int sh[256];
    int t = threadIdx.x;
    int b = blockIdx.x;
    int v = 0;
    for (int k = t; k < b; k += 256) v += g_bsum[k];
    sbase[t] = v;
    __syncthreads();
    for (int off = 128; off; off >>= 1) {
        if (t < off) sbase[t] += sbase[t + off];
        __syncthreads();
    }
    int base = sbase[0];
    int i = b * 256 + t;
    int c = (i < N_NODES) ? g_cnt[i] : 0;
    sh[t] = c;
    __syncthreads();
    for (int off = 1; off < 256; off <<= 1) {
        int a = (t >= off) ? sh[t - off] : 0;
        __syncthreads();
        sh[t] += a;
        __syncthreads();
    }
    if (i < N_NODES) {
        g_rowptr[i + 1] = base + sh[t];
        g_cnt[i] = 0;
    }
    if (i == 0) g_rowptr[0] = 0;
}

__global__ void scatter_kernel(const void* __restrict__ eidx) {
    int e = blockIdx.x * blockDim.x + threadIdx.x;
    if (e >= N_EDGES) return;
    int is64 = g_is64;
    int s = load_idx(eidx, e, is64);
    int d = load_idx(eidx, (long)N_EDGES + e, is64);
    int pos = g_rowptr[d] + atomicAdd(&g_cnt[d], 1);
    g_col[pos] = s;
}

__global__ __launch_bounds__(256) void pre_kernel(const float* __restrict__ x,
                                                  const float* __restrict__ w1a,
                                                  __half* __restrict__ u) {
    __shared__ float sX[NTILE * 68];
    __shared__ float sW[NFEAT * D];
    for (int i = threadIdx.x; i < NFEAT * D; i += 256) sW[i] = w1a[i];
    int base = blockIdx.x * NTILE;
    for (int i = threadIdx.x; i < NTILE * 16; i += 256) {
        int n = i >> 4, k4 = i & 15;
        int node = base + n;
        float4 v = make_float4(0.f, 0.f, 0.f, 0.f);
        if (node < N_NODES) v = ((const float4*)x)[(size_t)node * 16 + k4];
        *(float4*)&sX[n * 68 + k4 * 4] = v;
    }
    __syncthreads();
    int j0 = (threadIdx.x & 7) * 4;
    int n0 = (threadIdx.x >> 3) * 4;
    float acc[4][4];
#pragma unroll
    for (int i = 0; i < 4; i++)
#pragma unroll
        for (int j = 0; j < 4; j++) acc[i][j] = 0.f;
#pragma unroll 8
    for (int k = 0; k < NFEAT; k++) {
        float a0 = sX[(n0 + 0) * 68 + k];
        float a1 = sX[(n0 + 1) * 68 + k];
        float a2 = sX[(n0 + 2) * 68 + k];
        float a3 = sX[(n0 + 3) * 68 + k];
        float4 w = *(const float4*)&sW[k * D + j0];
        acc[0][0] = fmaf(a0, w.x, acc[0][0]); acc[0][1] = fmaf(a0, w.y, acc[0][1]);
        acc[0][2] = fmaf(a0, w.z, acc[0][2]); acc[0][3] = fmaf(a0, w.w, acc[0][3]);
        acc[1][0] = fmaf(a1, w.x, acc[1][0]); acc[1][1] = fmaf(a1, w.y, acc[1][1]);
        acc[1][2] = fmaf(a1, w.z, acc[1][2]); acc[1][3] = fmaf(a1, w.w, acc[1][3]);
        acc[2][0] = fmaf(a2, w.x, acc[2][0]); acc[2][1] = fmaf(a2, w.y, acc[2][1]);
        acc[2][2] = fmaf(a2, w.z, acc[2][2]); acc[2][3] = fmaf(a2, w.w, acc[2][3]);
        acc[3][0] = fmaf(a3, w.x, acc[3][0]); acc[3][1] = fmaf(a3, w.y, acc[3][1]);
        acc[3][2] = fmaf(a3, w.z, acc[3][2]); acc[3][3] = fmaf(a3, w.w, acc[3][3]);
    }
    __half2* u2 = (__half2*)u;
#pragma unroll
    for (int i = 0; i < 4; i++) {
        int node = base + n0 + i;
        if (node < N_NODES) {
            u2[(size_t)node * 16 + (j0 >> 1)] = __floats2half2_rn(acc[i][0], acc[i][1]);
            u2[(size_t)node * 16 + (j0 >> 1) + 1] = __floats2half2_rn(acc[i][2], acc[i][3]);
        }
    }
}

template <bool FIRST, bool OUTF32>
__global__ __launch_bounds__(256, 4) void layer_kernel(
    const __half* __restrict__ tin, const float* __restrict__ Wa,
    const float* __restrict__ ba, const float* __restrict__ Wb,
    const float* __restrict__ bb,
    const float* __restrict__ stats_in, float* __restrict__ stats_out,
    const float* __restrict__ bng, const float* __restrict__ bnb,
    __half* __restrict__ tout16, float* __restrict__ toutf) {
    __shared__ float sA[NTILE * 34];
    __shared__ float sWa[D * D];
    __shared__ float sWb[D * D];
    __shared__ float sba[D], sbb[D];
    __shared__ float sstat[64];
    int tid = threadIdx.x;
    if (!FIRST)
        for (int i = tid; i < D * D; i += 256) sWa[i] = Wa[i];
    for (int i = tid; i < D * D; i += 256) sWb[i] = Wb[i];
    if (tid < D) { sba[tid] = ba[tid]; sbb[tid] = bb[tid]; }
    if (tid < 64) sstat[tid] = 0.f;
    int lane = tid & 31, warp = tid >> 5;
    int f2 = lane & 15;
    int side = lane >> 4;
    float scx = 0.f, shx = 0.f, scy = 0.f, shy = 0.f;
    if (!FIRST) {
        int fx = 2 * f2, fy = 2 * f2 + 1;
        float Sx = stats_in[fx], Qx = stats_in[D + fx];
        float mux = Sx * (1.f / N_NODES);
        float vax = Qx * (1.f / N_NODES) - mux * mux;
        scx = rsqrtf(vax + BN_EPS) * bng[fx];
        shx = bnb[fx] - mux * scx;
        float Sy = stats_in[fy], Qy = stats_in[D + fy];
        float muy = Sy * (1.f / N_NODES);
        float vay = Qy * (1.f / N_NODES) - muy * muy;
        scy = rsqrtf(vay + BN_EPS) * bng[fy];
        shy = bnb[fy] - muy * scy;
    }
    __syncthreads();

    const __half2* tin2 = (const __half2*)tin;
    int base = blockIdx.x * NTILE;

    for (int r = 0; r < 16; r++) {
        int nl = warp * 16 + r;
        int node = base + nl;
        float ax = 0.f, ay = 0.f;
        if (node < N_NODES) {
            if (side == 0) {
                float2 v = __half22float2(tin2[(size_t)node * 16 + f2]);
                if (!FIRST) {
                    v.x = fmaxf(fmaf(v.x, scx, shx), 0.f);
                    v.y = fmaxf(fmaf(v.y, scy, shy), 0.f);
                }
                ax += v.x; ay += v.y;
            }
            int r0 = g_rowptr[node], r1 = g_rowptr[node + 1];
            for (int i = r0; i < r1; i += 16) {
                int cc[8];
                bool vb[8];
#pragma unroll
                for (int k = 0; k < 8; k++) {
                    int idx = i + 2 * k + side;
                    vb[k] = idx < r1;
                    cc[k] = g_col[vb[k] ? idx : (r1 - 1)];
                }
                float2 vv[8];
#pragma unroll
                for (int k = 0; k < 8; k++)
                    vv[k] = __half22float2(tin2[(size_t)cc[k] * 16 + f2]);
#pragma unroll
                for (int k = 0; k < 8; k++) {
                    if (vb[k]) {
                        float vx = vv[k].x, vy = vv[k].y;
                        if (!FIRST) {
                            vx = fmaxf(fmaf(vx, scx, shx), 0.f);
                            vy = fmaxf(fmaf(vy, scy, shy), 0.f);
                        }
                        ax += vx; ay += vy;
                    }
                }
            }
        }
        ax += __shfl_xor_sync(0xffffffffu, ax, 16);
        ay += __shfl_xor_sync(0xffffffffu, ay, 16);
        if (side == 0) {
            if (FIRST) {
                ax = fmaxf(ax + sba[2 * f2], 0.f);
                ay = fmaxf(ay + sba[2 * f2 + 1], 0.f);
            }
            *(float2*)&sA[nl * 34 + 2 * f2] = make_float2(ax, ay);
        }
    }
    __syncthreads();

    int j0 = (tid & 7) * 4;
    int n0 = (tid >> 3) * 4;

    if (!FIRST) {
        float acc[4][4];
#pragma unroll
        for (int i = 0; i < 4; i++)
#pragma unroll
            for (int j = 0; j < 4; j++) acc[i][j] = 0.f;
#pragma unroll
        for (int k = 0; k < D; k++) {
            float a0 = sA[(n0 + 0) * 34 + k];
            float a1 = sA[(n0 + 1) * 34 + k];
            float a2 = sA[(n0 + 2) * 34 + k];
            float a3 = sA[(n0 + 3) * 34 + k];
            float4 w = *(const float4*)&sWa[k * D + j0];
            acc[0][0] = fmaf(a0, w.x, acc[0][0]); acc[0][1] = fmaf(a0, w.y, acc[0][1]);
            acc[0][2] = fmaf(a0, w.z, acc[0][2]); acc[0][3] = fmaf(a0, w.w, acc[0][3]);
            acc[1][0] = fmaf(a1, w.x, acc[1][0]); acc[1][1] = fmaf(a1, w.y, acc[1][1]);
            acc[1][2] = fmaf(a1, w.z, acc[1][2]); acc[1][3] = fmaf(a1, w.w, acc[1][3]);
            acc[2][0] = fmaf(a2, w.x, acc[2][0]); acc[2][1] = fmaf(a2, w.y, acc[2][1]);
            acc[2][2] = fmaf(a2, w.z, acc[2][2]); acc[2][3] = fmaf(a2, w.w, acc[2][3]);
            acc[3][0] = fmaf(a3, w.x, acc[3][0]); acc[3][1] = fmaf(a3, w.y, acc[3][1]);
            acc[3][2] = fmaf(a3, w.z, acc[3][2]); acc[3][3] = fmaf(a3, w.w, acc[3][3]);
        }
        __syncthreads();
#pragma unroll
        for (int i = 0; i < 4; i++)
#pragma unroll
            for (int j = 0; j < 4; j++)
                sA[(n0 + i) * 34 + j0 + j] = fmaxf(acc[i][j] + sba[j0 + j], 0.f);
        __syncthreads();
    }

    float acc2[4][4];
#pragma unroll
    for (int i = 0; i < 4; i++)
#pragma unroll
        for (int j = 0; j < 4; j++) acc2[i][j] = 0.f;
#pragma unroll
    for (int k = 0; k < D; k++) {
        float a0 = sA[(n0 + 0) * 34 + k];
        float a1 = sA[(n0 + 1) * 34 + k];
        float a2 = sA[(n0 + 2) * 34 + k];
        float a3 = sA[(n0 + 3) * 34 + k];
        float4 w = *(const float4*)&sWb[k * D + j0];
        acc2[0][0] = fmaf(a0, w.x, acc2[0][0]); acc2[0][1] = fmaf(a0, w.y, acc2[0][1]);
        acc2[0][2] = fmaf(a0, w.z, acc2[0][2]); acc2[0][3] = fmaf(a0, w.w, acc2[0][3]);
        acc2[1][0] = fmaf(a1, w.x, acc2[1][0]); acc2[1][1] = fmaf(a1, w.y, acc2[1][1]);
        acc2[1][2] = fmaf(a1, w.z, acc2[1][2]); acc2[1][3] = fmaf(a1, w.w, acc2[1][3]);
        acc2[2][0] = fmaf(a2, w.x, acc2[2][0]); acc2[2][1] = fmaf(a2, w.y, acc2[2][1]);
        acc2[2][2] = fmaf(a2, w.z, acc2[2][2]); acc2[2][3] = fmaf(a2, w.w, acc2[2][3]);
        acc2[3][0] = fmaf(a3, w.x, acc2[3][0]); acc2[3][1] = fmaf(a3, w.y, acc2[3][1]);
        acc2[3][2] = fmaf(a3, w.z, acc2[3][2]); acc2[3][3] = fmaf(a3, w.w, acc2[3][3]);
    }
    float colS[4] = {0.f, 0.f, 0.f, 0.f};
    float colQ[4] = {0.f, 0.f, 0.f, 0.f};
    __half2* t2 = (__half2*)tout16;
#pragma unroll
    for (int i = 0; i < 4; i++) {
        int node = base + n0 + i;
        if (node < N_NODES) {
            float z0 = acc2[i][0] + sbb[j0 + 0];
            float z1 = acc2[i][1] + sbb[j0 + 1];
            float z2 = acc2[i][2] + sbb[j0 + 2];
            float z3 = acc2[i][3] + sbb[j0 + 3];
            if (OUTF32) {
                *(float4*)&toutf[(size_t)node * D + j0] = make_float4(z0, z1, z2, z3);
            } else {
                t2[(size_t)node * 16 + (j0 >> 1)] = __floats2half2_rn(z0, z1);
                t2[(size_t)node * 16 + (j0 >> 1) + 1] = __floats2half2_rn(z2, z3);
            }
            colS[0] += z0; colS[1] += z1; colS[2] += z2; colS[3] += z3;
            colQ[0] += z0 * z0; colQ[1] += z1 * z1; colQ[2] += z2 * z2; colQ[3] += z3 * z3;
        }
    }
#pragma unroll
    for (int j = 0; j < 4; j++) {
        atomicAdd(&sstat[j0 + j], colS[j]);
        atomicAdd(&sstat[32 + j0 + j], colQ[j]);
    }
    __syncthreads();
    if (tid < 64) redf(&stats_out[tid], sstat[tid]);
}

__global__ __launch_bounds__(256) void pool_kernel(const float* __restrict__ t,
                                                   const void* __restrict__ batch,
                                                   const float* __restrict__ stats,
                                                   const float* __restrict__ bng,
                                                   const float* __restrict__ bnb) {
    __shared__ float ssc[D], ssh[D];
    if (threadIdx.x < D) {
        int f = threadIdx.x;
        float S = stats[f], Q = stats[D + f];
        float mu = S * (1.f / N_NODES);
        float var = Q * (1.f / N_NODES) - mu * mu;
        float rs = rsqrtf(var + BN_EPS);
        float sc = rs * bng[f];
        ssc[f] = sc;
        ssh[f] = bnb[f] - mu * sc;
    }
    __syncthreads();
    int i = blockIdx.x * blockDim.x + threadIdx.x;
    if (i >= N_NODES * (D / 4)) return;
    int node = i >> 3;
    int j = i & 7;
    int b = load_idx(batch, node, g_is64);
    float4 v = ((const float4*)t)[i];
    float4 o;
    o.x = fmaxf(fmaf(v.x, ssc[j * 4 + 0], ssh[j * 4 + 0]), 0.f);
    o.y = fmaxf(fmaf(v.y, ssc[j * 4 + 1], ssh[j * 4 + 1]), 0.f);
    o.z = fmaxf(fmaf(v.z, ssc[j * 4 + 2], ssh[j * 4 + 2]), 0.f);
    o.w = fmaxf(fmaf(v.w, ssc[j * 4 + 3], ssh[j * 4 + 3]), 0.f);
    float* p = g_pooled + (size_t)b * D + j * 4;
    asm volatile("red.global.add.v4.f32 [%0], {%1,%2,%3,%4};"
                 :: "l"(p), "f"(o.x), "f"(o.y), "f"(o.z), "f"(o.w) : "memory");
}

// ---------------- wmma fp16 GEMM, 64x64 tile, 8 warps ----------------
// EPI 0: C = acc + bias                       (fc1_bottom)
// EPI 1: Ch = relu(acc + C)                   (fc1_top)
// EPI 2: out[row] += relu(acc+bias).ow  (+ob) (fc2 + output projection)
// EPI 3: Ch = relu(acc + bias)                (fs1 / fs2 / gfeat)
template <int EPI>
__global__ __launch_bounds__(256) void wgemm_kernel(
    const __half* __restrict__ A, int lda,
    const __half* __restrict__ B, int ldb,
    const float* __restrict__ bias,
    float* __restrict__ C, int ldc,
    __half* __restrict__ Ch, int K,
    const float* __restrict__ ow, const float* __restrict__ ob,
    float* __restrict__ outp) {
    __shared__ __half As[64][24];
    __shared__ __half Bs[16][72];
    __shared__ float Cs[64][68];
    int tid = threadIdx.x;
    int warp = tid >> 5;
    int wy = warp >> 1, wx = warp & 1;
    int row0 = blockIdx.y * 64;
    int col0 = blockIdx.x * 64;

    wmma::fragment<wmma::accumulator, 16, 16, 16, float> acc0, acc1;
    wmma::fill_fragment(acc0, 0.f);
    wmma::fill_fragment(acc1, 0.f);

    int arow = tid >> 2, acol = (tid & 3) * 4;
    int brow = tid >> 4, bcol = (tid & 15) * 4;

    for (int kt = 0; kt < K; kt += 16) {
        *(uint2*)&As[arow][acol] = *(const uint2*)&A[(size_t)(row0 + arow) * lda + kt + acol];
        *(uint2*)&Bs[brow][bcol] = *(const uint2*)&B[(size_t)(kt + brow) * ldb + col0 + bcol];
        __syncthreads();
        wmma::fragment<wmma::matrix_a, 16, 16, 16, __half, wmma::row_major> af;
        wmma::fragment<wmma::matrix_b, 16, 16, 16, __half, wmma::row_major> bf0, bf1;
        wmma::load_matrix_sync(af, &As[wy * 16][0], 24);
        wmma::load_matrix_sync(bf0, &Bs[0][wx * 32], 72);
        wmma::load_matrix_sync(bf1, &Bs[0][wx * 32 + 16], 72);
        wmma::mma_sync(acc0, af, bf0, acc0);
        wmma::mma_sync(acc1, af, bf1, acc1);
        __syncthreads();
    }
    wmma::store_matrix_sync(&Cs[wy * 16][wx * 32], acc0, 68, wmma::mem_row_major);
    wmma::store_matrix_sync(&Cs[wy * 16][wx * 32 + 16], acc1, 68, wmma::mem_row_major);
    __syncthreads();
    if (EPI == 2) {
        // fused output projection: 4 threads per row, 16 cols each
        int r = tid >> 2, q = tid & 3;
        float p = 0.f;
#pragma unroll
        for (int c0 = 0; c0 < 16; c0++) {
            int c = q * 16 + c0;
            float v = fmaxf(Cs[r][c] + bias[col0 + c], 0.f);
            p = fmaf(v, ow[col0 + c], p);
        }
        p += __shfl_down_sync(0xffffffffu, p, 2);
        p += __shfl_down_sync(0xffffffffu, p, 1);
        if (q == 0) {
            if (blockIdx.x == 0) p += ob[0];
            atomicAdd(&outp[row0 + r], p);
        }
    } else {
        for (int i = tid; i < 64 * 64; i += 256) {
            int r = i >> 6, c = i & 63;
            int rr = row0 + r, cc = col0 + c;
            float v = Cs[r][c];
            if (EPI == 0) {
                C[(size_t)rr * ldc + cc] = v + bias[cc];
            } else if (EPI == 1) {
                v += C[(size_t)rr * ldc + cc];
                Ch[(size_t)rr * ldc + cc] = __float2half(fmaxf(v, 0.f));
            } else {  // EPI 3
                Ch[(size_t)rr * ldc + cc] = __float2half(fmaxf(v + bias[cc], 0.f));
            }
        }
    }
}

extern "C" void kernel_launch(void* const* d_in, const int* in_sizes, int n_in,
                              void* d_out, int out_size) {
    const float* x     = (const float*)d_in[0];
    const void*  eidx  = d_in[1];
    const void*  batch = d_in[2];
    const float* sfp   = (const float*)d_in[3];
    const float* w1a   = (const float*)d_in[4];
    const float* b1a   = (const float*)d_in[5];
    const float* ws_a  = (const float*)d_in[6];
    const float* bs_a  = (const float*)d_in[7];
    const float* ws_b  = (const float*)d_in[8];
    const float* bs_b  = (const float*)d_in[9];
    const float* bn_g  = (const float*)d_in[10];
    const float* bn_b  = (const float*)d_in[11];
    const float* fcg_w = (const float*)d_in[12];
    const float* fcg_b = (const float*)d_in[13];
    const float* fs1_w = (const float*)d_in[14];
    const float* fs1_b = (const float*)d_in[15];
    const float* fs2_w = (const float*)d_in[16];
    const float* fs2_b = (const float*)d_in[17];
    const float* fc1_w = (const float*)d_in[18];
    const float* fc1_b = (const float*)d_in[19];
    const float* fc2_w = (const float*)d_in[20];
    const float* fc2_b = (const float*)d_in[21];
    const float* out_w = (const float*)d_in[22];
    const float* out_b = (const float*)d_in[23];
    float* out = (float*)d_out;

    __half *ha, *hb, *zh, *z1h, *fc1wh, *fc2wh, *sfph, *s1h, *pooledh, *fs1wh, *fs2wh, *fcgwh;
    float *tf, *pooled, *z1, *statsf;
    cudaGetSymbolAddress((void**)&ha, g_ha);
    cudaGetSymbolAddress((void**)&hb, g_hb);
    cudaGetSymbolAddress((void**)&zh, g_zh);
    cudaGetSymbolAddress((void**)&z1h, g_z1h);
    cudaGetSymbolAddress((void**)&fc1wh, g_fc1wh);
    cudaGetSymbolAddress((void**)&fc2wh, g_fc2wh);
    cudaGetSymbolAddress((void**)&sfph, g_sfph);
    cudaGetSymbolAddress((void**)&s1h, g_s1h);
    cudaGetSymbolAddress((void**)&pooledh, g_pooledh);
    cudaGetSymbolAddress((void**)&fs1wh, g_fs1wh);
    cudaGetSymbolAddress((void**)&fs2wh, g_fs2wh);
    cudaGetSymbolAddress((void**)&fcgwh, g_fcgwh);
    cudaGetSymbolAddress((void**)&tf, g_tf);
    cudaGetSymbolAddress((void**)&pooled, g_pooled);
    cudaGetSymbolAddress((void**)&z1, g_z1);
    cudaGetSymbolAddress((void**)&statsf, g_statsf);

    static cudaStream_t sA = nullptr, sB = nullptr;
    static cudaEvent_t evRoot = nullptr, evA = nullptr, evB = nullptr;
    if (!sA) {
        cudaStreamCreateWithFlags(&sA, cudaStreamNonBlocking);
        cudaStreamCreateWithFlags(&sB, cudaStreamNonBlocking);
        cudaEventCreateWithFlags(&evRoot, cudaEventDisableTiming);
        cudaEventCreateWithFlags(&evA, cudaEventDisableTiming);
        cudaEventCreateWithFlags(&evB, cudaEventDisableTiming);
    }

    const int TB = 256;

    cudaEventRecord(evRoot, 0);
    cudaStreamWaitEvent(sA, evRoot, 0);
    cudaStreamWaitEvent(sB, evRoot, 0);

    // 0: init
    init_kernel<<<(N_NODES + TB - 1) / TB, TB>>>(eidx, out);

    // Branch B: convW(1) -> convS(2) -> fs1(3, captured) -> fs2(4) -> fc1_bottom(5)
    convW_kernel<<<(256 * 1024 + TB - 1) / TB, TB, 0, sB>>>(fc1_w, fc2_w, fs1_w, fs2_w, fcg_w);
    convS_kernel<<<(G_GRAPHS * SFD + TB - 1) / TB, TB, 0, sB>>>(sfp);
    wgemm_kernel<3><<<dim3(4, 32), 256, 0, sB>>>(
        sfph, SFD, fs1wh, 256, fs1_b, nullptr, 256, s1h, SFD, nullptr, nullptr, nullptr);
    wgemm_kernel<3><<<dim3(2, 32), 256, 0, sB>>>(
        s1h, 256, fs2wh, 128, fs2_b, nullptr, 256, zh + 128, 256, nullptr, nullptr, nullptr);
    wgemm_kernel<0><<<dim3(16, 32), 256, 0, sB>>>(
        zh + 128, 256, fc1wh + 128 * 1024, 1024, fc1_b, z1, 1024, nullptr, 128,
        nullptr, nullptr, nullptr);
    cudaEventRecord(evB, sB);

    // Branch A: pre-transform
    pre_kernel<<<NBLK_TILE, 256, 0, sA>>>(x, w1a, ha);
    cudaEventRecord(evA, sA);

    // Main: CSR build
    hist_kernel<<<(N_EDGES + TB - 1) / TB, TB>>>(eidx);
    scanA_kernel<<<NBLK_SCAN, 256>>>();
    scanC_kernel<<<NBLK_SCAN, 256>>>();
    scatter_kernel<<<(N_EDGES + TB - 1) / TB, TB>>>(eidx);

    // layers
    cudaStreamWaitEvent(0, evA, 0);
    layer_kernel<true, false><<<NBLK_TILE, 256>>>(ha, nullptr, b1a, ws_b, bs_b,
                                                  nullptr, statsf, nullptr, nullptr,
                                                  hb, nullptr);
    __half* tin = hb;
    __half* tout = ha;
    for (int l = 1; l < 4; l++) {
        layer_kernel<false, false><<<NBLK_TILE, 256>>>(
            tin, ws_a + (l - 1) * D * D, bs_a + (l - 1) * D,
            ws_b + l * D * D, bs_b + l * D,
            statsf + (l - 1) * 64, statsf + l * 64,
            bn_g + (l - 1) * D, bn_b + (l - 1) * D, tout, nullptr);
        __half* tmp = tin; tin = tout; tout = tmp;
    }
    layer_kernel<false, true><<<NBLK_TILE, 256>>>(
        tin, ws_a + 3 * D * D, bs_a + 3 * D,
        ws_b + 4 * D * D, bs_b + 4 * D,
        statsf + 3 * 64, statsf + 4 * 64,
        bn_g + 3 * D, bn_b + 3 * D, nullptr, tf);

    // pooling -> fp16 -> gfeat (wmma, fp16 out into left half of zh)
    pool_kernel<<<(N_NODES * 8 + TB - 1) / TB, TB>>>(tf, batch, statsf + 4 * 64,
                                                     bn_g + 4 * D, bn_b + 4 * D);
    pconv_kernel<<<(G_GRAPHS * D + TB - 1) / TB, TB>>>();
    wgemm_kernel<3><<<dim3(2, 32), 256>>>(
        pooledh, D, fcgwh, 128, fcg_b, nullptr, 256, zh, D, nullptr, nullptr, nullptr);

    // join solvent branch; fc1_top (wmma) ; fc2 + output projection fused (wmma)
    cudaStreamWaitEvent(0, evB, 0);
    wgemm_kernel<1><<<dim3(16, 32), 256>>>(
        zh, 256, fc1wh, 1024, nullptr, z1, 1024, z1h, 128, nullptr, nullptr, nullptr);
    wgemm_kernel<2><<<dim3(4, 32), 256>>>(
        z1h, 1024, fc2wh, 256, fc2_b, nullptr, 256, nullptr, 1024, out_w, out_b, out);
}